// round 2
// baseline (speedup 1.0000x reference)
#include <cuda_runtime.h>
#include <math.h>

// Problem constants
#define BATCH 8
#define MDIM  16384   // S*K = 512*32
#define DDIM  512

// GEMM tiling
#define BM 128
#define BN 128
#define BK 16

// Scratch (static device globals; no allocations allowed)
__device__ float g_energy[BATCH * DDIM * DDIM];  // G = X^T X   (8 MB)
__device__ float g_att[BATCH * DDIM * DDIM];     // A^T          (8 MB)

// ---------------------------------------------------------------------------
// Kernel 1: Gram matrix  G[b] = X^T X,  X = x[b] as [M, D] row-major.
// Tile: 128x128 output, BK=16 reduction chunk, 256 threads, 8x8 per thread.
// grid = (D/BN, D/BM, BATCH)
// ---------------------------------------------------------------------------
__global__ __launch_bounds__(256, 2) void gram_kernel(const float* __restrict__ x) {
    const int b  = blockIdx.z;
    const int d0 = blockIdx.y * BM;   // output rows  (d)
    const int e0 = blockIdx.x * BN;   // output cols  (e)
    const float* __restrict__ X = x + (size_t)b * MDIM * DDIM;
    float* __restrict__ G = g_energy + (size_t)b * DDIM * DDIM;

    __shared__ float As[BK][BM];
    __shared__ float Bs[BK][BN];

    const int tid = threadIdx.x;
    const int tx  = tid & 15;   // 0..15 -> cols
    const int ty  = tid >> 4;   // 0..15 -> rows

    float acc[8][8];
#pragma unroll
    for (int i = 0; i < 8; i++)
#pragma unroll
        for (int j = 0; j < 8; j++) acc[i][j] = 0.f;

    for (int kt = 0; kt < MDIM; kt += BK) {
        // Load BK rows of X, 128 cols for each panel. Rows are contiguous.
#pragma unroll
        for (int it = 0; it < 2; it++) {
            int fid = tid + it * 256;          // 0..511
            int r   = fid >> 5;                // 0..15  (k within chunk)
            int c   = (fid & 31) << 2;         // 0..124 (float4 col)
            const float* rowp = X + (size_t)(kt + r) * DDIM;
            float4 va = *reinterpret_cast<const float4*>(rowp + d0 + c);
            *reinterpret_cast<float4*>(&As[r][c]) = va;
            float4 vb = *reinterpret_cast<const float4*>(rowp + e0 + c);
            *reinterpret_cast<float4*>(&Bs[r][c]) = vb;
        }
        __syncthreads();

#pragma unroll
        for (int k = 0; k < BK; k++) {
            float a[8], bv[8];
            *reinterpret_cast<float4*>(&a[0])  = *reinterpret_cast<float4*>(&As[k][ty * 8]);
            *reinterpret_cast<float4*>(&a[4])  = *reinterpret_cast<float4*>(&As[k][ty * 8 + 4]);
            *reinterpret_cast<float4*>(&bv[0]) = *reinterpret_cast<float4*>(&Bs[k][tx * 8]);
            *reinterpret_cast<float4*>(&bv[4]) = *reinterpret_cast<float4*>(&Bs[k][tx * 8 + 4]);
#pragma unroll
            for (int i = 0; i < 8; i++)
#pragma unroll
                for (int j = 0; j < 8; j++)
                    acc[i][j] = fmaf(a[i], bv[j], acc[i][j]);
        }
        __syncthreads();
    }

    // Store G tile
#pragma unroll
    for (int i = 0; i < 8; i++) {
        float* gp = G + (size_t)(d0 + ty * 8 + i) * DDIM + e0 + tx * 8;
#pragma unroll
        for (int jq = 0; jq < 2; jq++) {
            float4 r;
            r.x = acc[i][jq * 4 + 0];
            r.y = acc[i][jq * 4 + 1];
            r.z = acc[i][jq * 4 + 2];
            r.w = acc[i][jq * 4 + 3];
            *reinterpret_cast<float4*>(gp + jq * 4) = r;
        }
    }
}

// ---------------------------------------------------------------------------
// Kernel 2: row-wise softmax of (-G); writes A^T so GEMM2's B is row-major.
// softmax(rowmax - G) == softmax(-G); stable form: exp(min(G) - G_e) / sum.
// grid = (DDIM, BATCH), 256 threads (2 elems each).
// ---------------------------------------------------------------------------
__global__ void softmax_kernel() {
    const int b = blockIdx.y;
    const int d = blockIdx.x;
    const float* __restrict__ Grow = g_energy + (size_t)b * DDIM * DDIM + (size_t)d * DDIM;
    float* __restrict__ At = g_att + (size_t)b * DDIM * DDIM;

    __shared__ float red[256];
    const int t = threadIdx.x;

    float v0 = Grow[t];
    float v1 = Grow[t + 256];

    // min over row
    red[t] = fminf(v0, v1);
    __syncthreads();
#pragma unroll
    for (int s = 128; s > 0; s >>= 1) {
        if (t < s) red[t] = fminf(red[t], red[t + s]);
        __syncthreads();
    }
    const float gmin = red[0];
    __syncthreads();

    float p0 = expf(gmin - v0);
    float p1 = expf(gmin - v1);

    red[t] = p0 + p1;
    __syncthreads();
#pragma unroll
    for (int s = 128; s > 0; s >>= 1) {
        if (t < s) red[t] += red[t + s];
        __syncthreads();
    }
    const float inv = 1.f / red[0];

    At[(size_t)t * DDIM + d]         = p0 * inv;
    At[(size_t)(t + 256) * DDIM + d] = p1 * inv;
}

// ---------------------------------------------------------------------------
// Kernel 3: Y = gamma * (X @ A^T) + X, written to d_out.
// C[m, d] = sum_e X[m, e] * At[e, d].  grid = (D/BN, M/BM, BATCH).
// ---------------------------------------------------------------------------
__global__ __launch_bounds__(256, 2) void gemm2_kernel(const float* __restrict__ x,
                                                       const float* __restrict__ gam,
                                                       float* __restrict__ out) {
    const int b  = blockIdx.z;
    const int d0 = blockIdx.x * BN;   // output cols (d)
    const int m0 = blockIdx.y * BM;   // output rows (m)
    const float* __restrict__ X  = x + (size_t)b * MDIM * DDIM;
    const float* __restrict__ At = g_att + (size_t)b * DDIM * DDIM;
    float* __restrict__ Y = out + (size_t)b * MDIM * DDIM;

    __shared__ float As[BK][BM];   // As[k][i] = X[m0+i, ec+k]   (transposed on store)
    __shared__ float Bs[BK][BN];   // Bs[k][j] = At[ec+k, d0+j]

    const int tid = threadIdx.x;
    const int tx  = tid & 15;
    const int ty  = tid >> 4;

    float acc[8][8];
#pragma unroll
    for (int i = 0; i < 8; i++)
#pragma unroll
        for (int j = 0; j < 8; j++) acc[i][j] = 0.f;

    for (int ec = 0; ec < DDIM; ec += BK) {
        // A panel: [BM m-rows] x [BK e-cols], loaded row-contiguous, stored transposed
#pragma unroll
        for (int it = 0; it < 2; it++) {
            int fid = tid + it * 256;          // 0..511
            int row = fid >> 2;                // 0..127 (m within tile)
            int cq  = (fid & 3) << 2;          // 0,4,8,12 (e within chunk)
            float4 va = *reinterpret_cast<const float4*>(
                X + (size_t)(m0 + row) * DDIM + ec + cq);
            As[cq + 0][row] = va.x;
            As[cq + 1][row] = va.y;
            As[cq + 2][row] = va.z;
            As[cq + 3][row] = va.w;
        }
        // B panel: BK rows of At, contiguous
#pragma unroll
        for (int it = 0; it < 2; it++) {
            int fid = tid + it * 256;
            int r   = fid >> 5;                // 0..15
            int c   = (fid & 31) << 2;         // 0..124
            float4 vb = *reinterpret_cast<const float4*>(
                At + (size_t)(ec + r) * DDIM + d0 + c);
            *reinterpret_cast<float4*>(&Bs[r][c]) = vb;
        }
        __syncthreads();

#pragma unroll
        for (int k = 0; k < BK; k++) {
            float a[8], bv[8];
            *reinterpret_cast<float4*>(&a[0])  = *reinterpret_cast<float4*>(&As[k][ty * 8]);
            *reinterpret_cast<float4*>(&a[4])  = *reinterpret_cast<float4*>(&As[k][ty * 8 + 4]);
            *reinterpret_cast<float4*>(&bv[0]) = *reinterpret_cast<float4*>(&Bs[k][tx * 8]);
            *reinterpret_cast<float4*>(&bv[4]) = *reinterpret_cast<float4*>(&Bs[k][tx * 8 + 4]);
#pragma unroll
            for (int i = 0; i < 8; i++)
#pragma unroll
                for (int j = 0; j < 8; j++)
                    acc[i][j] = fmaf(a[i], bv[j], acc[i][j]);
        }
        __syncthreads();
    }

    // Epilogue: Y = gamma * C + X
    const float g = gam[0];
#pragma unroll
    for (int i = 0; i < 8; i++) {
        size_t roff = (size_t)(m0 + ty * 8 + i) * DDIM + d0 + tx * 8;
#pragma unroll
        for (int jq = 0; jq < 2; jq++) {
            float4 xv = *reinterpret_cast<const float4*>(X + roff + jq * 4);
            float4 r;
            r.x = g * acc[i][jq * 4 + 0] + xv.x;
            r.y = g * acc[i][jq * 4 + 1] + xv.y;
            r.z = g * acc[i][jq * 4 + 2] + xv.z;
            r.w = g * acc[i][jq * 4 + 3] + xv.w;
            *reinterpret_cast<float4*>(Y + roff + jq * 4) = r;
        }
    }
}

// ---------------------------------------------------------------------------
extern "C" void kernel_launch(void* const* d_in, const int* in_sizes, int n_in,
                              void* d_out, int out_size) {
    const float* x     = (const float*)d_in[0];
    const float* gamma = (const float*)d_in[1];
    float* out = (float*)d_out;

    gram_kernel<<<dim3(DDIM / BN, DDIM / BM, BATCH), 256>>>(x);
    softmax_kernel<<<dim3(DDIM, BATCH), 256>>>();
    gemm2_kernel<<<dim3(DDIM / BN, MDIM / BM, BATCH), 256>>>(x, gamma, out);
}

// round 5
// speedup vs baseline: 2.8056x; 2.8056x over previous
#include <cuda_runtime.h>
#include <cuda_bf16.h>
#include <cstdint>
#include <math.h>

#define BATCH 8
#define MDIM  16384
#define DDIM  512

// ---------------- scratch (device globals; no allocations allowed) ----------
__device__ __nv_bfloat16 g_x_hi[(size_t)BATCH * MDIM * DDIM];    // X hi (128MB)
__device__ __nv_bfloat16 g_x_lo[(size_t)BATCH * MDIM * DDIM];    // X lo (128MB)
__device__ float         g_energy[(size_t)BATCH * DDIM * DDIM];  // G    (8MB)
__device__ __nv_bfloat16 g_att_hi[(size_t)BATCH * DDIM * DDIM];  // A hi (4MB)
__device__ __nv_bfloat16 g_att_lo[(size_t)BATCH * DDIM * DDIM];  // A lo (4MB)

// ---------------- helpers ----------------
__device__ __forceinline__ uint32_t smem_u32(const void* p) {
    uint32_t a;
    asm("{ .reg .u64 t; cvta.to.shared.u64 t, %1; cvt.u32.u64 %0, t; }" : "=r"(a) : "l"(p));
    return a;
}
__device__ __forceinline__ void cp16(uint32_t dst, const void* src) {
    asm volatile("cp.async.cg.shared.global [%0], [%1], 16;" :: "r"(dst), "l"(src));
}
#define CP_COMMIT() asm volatile("cp.async.commit_group;" ::: "memory")
#define CP_WAIT(n)  asm volatile("cp.async.wait_group %0;" :: "n"(n) : "memory")

__device__ __forceinline__ void mma_bf16(float* c, const uint32_t* a, const uint32_t* b) {
    asm volatile(
        "mma.sync.aligned.m16n8k16.row.col.f32.bf16.bf16.f32 "
        "{%0,%1,%2,%3}, {%4,%5,%6,%7}, {%8,%9}, {%0,%1,%2,%3};"
        : "+f"(c[0]), "+f"(c[1]), "+f"(c[2]), "+f"(c[3])
        : "r"(a[0]), "r"(a[1]), "r"(a[2]), "r"(a[3]), "r"(b[0]), "r"(b[1]));
}
__device__ __forceinline__ void ldsm4(uint32_t* r, uint32_t a) {
    asm volatile("ldmatrix.sync.aligned.m8n8.x4.shared.b16 {%0,%1,%2,%3}, [%4];"
                 : "=r"(r[0]), "=r"(r[1]), "=r"(r[2]), "=r"(r[3]) : "r"(a));
}
__device__ __forceinline__ void ldsm4t(uint32_t* r, uint32_t a) {
    asm volatile("ldmatrix.sync.aligned.m8n8.x4.trans.shared.b16 {%0,%1,%2,%3}, [%4];"
                 : "=r"(r[0]), "=r"(r[1]), "=r"(r[2]), "=r"(r[3]) : "r"(a));
}
__device__ __forceinline__ void ldsm2(uint32_t* r, uint32_t a) {
    asm volatile("ldmatrix.sync.aligned.m8n8.x2.shared.b16 {%0,%1}, [%2];"
                 : "=r"(r[0]), "=r"(r[1]) : "r"(a));
}
__device__ __forceinline__ void ldsm2t(uint32_t* r, uint32_t a) {
    asm volatile("ldmatrix.sync.aligned.m8n8.x2.trans.shared.b16 {%0,%1}, [%2];"
                 : "=r"(r[0]), "=r"(r[1]) : "r"(a));
}

// ---------------------------------------------------------------------------
// Kernel 0: bf16 hi/lo split of x (natural [m, d] layout)
// ---------------------------------------------------------------------------
__global__ void split_kernel(const float* __restrict__ x) {
    const size_t n4 = (size_t)BATCH * MDIM * DDIM / 4;
    const size_t stride = (size_t)gridDim.x * blockDim.x;
    for (size_t i = (size_t)blockIdx.x * blockDim.x + threadIdx.x; i < n4; i += stride) {
        float4 v = reinterpret_cast<const float4*>(x)[i];
        __nv_bfloat16 h0 = __float2bfloat16(v.x), h1 = __float2bfloat16(v.y);
        __nv_bfloat16 h2 = __float2bfloat16(v.z), h3 = __float2bfloat16(v.w);
        __nv_bfloat16 l0 = __float2bfloat16(v.x - __bfloat162float(h0));
        __nv_bfloat16 l1 = __float2bfloat16(v.y - __bfloat162float(h1));
        __nv_bfloat16 l2 = __float2bfloat16(v.z - __bfloat162float(h2));
        __nv_bfloat16 l3 = __float2bfloat16(v.w - __bfloat162float(h3));
        uint2 hw, lw;
        hw.x = ((uint32_t)__bfloat16_as_ushort(h1) << 16) | __bfloat16_as_ushort(h0);
        hw.y = ((uint32_t)__bfloat16_as_ushort(h3) << 16) | __bfloat16_as_ushort(h2);
        lw.x = ((uint32_t)__bfloat16_as_ushort(l1) << 16) | __bfloat16_as_ushort(l0);
        lw.y = ((uint32_t)__bfloat16_as_ushort(l3) << 16) | __bfloat16_as_ushort(l2);
        reinterpret_cast<uint2*>(g_x_hi)[i] = hw;
        reinterpret_cast<uint2*>(g_x_lo)[i] = lw;
    }
}

// ---------------------------------------------------------------------------
// Kernel 1: Gram via mma.sync.  G[d,e] = sum_m X[m,d]*X[m,e]
// CTA tile 128x128, BK=64 over m, cp.async double buffer, trans ldmatrix.
// Smem panel: [64 m-rows][128 cols + 8 pad] bf16, row stride 272B.
// ---------------------------------------------------------------------------
#define G_LDA   272
#define G_TILE  (64 * G_LDA)      // 17408
#define G_STAGE (4 * G_TILE)      // 69632
#define G_SMEM  (2 * G_STAGE)     // 139264

__device__ __forceinline__ void gram_load(uint32_t dst, const char* Ah, const char* Al,
                                          const char* Bh, const char* Bl, int m0, int tid) {
    const char* srcs[4] = {Ah, Al, Bh, Bl};
#pragma unroll
    for (int t = 0; t < 4; t++) {
        uint32_t db = dst + t * G_TILE;
        const char* sp = srcs[t] + (size_t)m0 * 1024;
#pragma unroll
        for (int j = 0; j < 4; j++) {
            int idx = tid + j * 256;
            int row = idx >> 4, c16 = idx & 15;
            cp16(db + row * G_LDA + c16 * 16, sp + (size_t)row * 1024 + c16 * 16);
        }
    }
}

extern __shared__ char dyn_smem[];

__global__ __launch_bounds__(256, 1) void gram_mma_kernel() {
    const uint32_t sb = smem_u32(dyn_smem);
    const int tid = threadIdx.x, l = tid & 31, w = tid >> 5;
    const int wd = w & 1, we = w >> 1;            // warp tile: 64 (d) x 32 (e)
    const int b = blockIdx.z, d0 = blockIdx.y * 128, e0 = blockIdx.x * 128;

    const char* xh = (const char*)(g_x_hi + (size_t)b * MDIM * DDIM);
    const char* xl = (const char*)(g_x_lo + (size_t)b * MDIM * DDIM);
    const char* pAh = xh + d0 * 2;
    const char* pAl = xl + d0 * 2;
    const char* pBh = xh + e0 * 2;
    const char* pBl = xl + e0 * 2;

    float c[4][4][4];
#pragma unroll
    for (int i = 0; i < 4; i++)
#pragma unroll
        for (int j = 0; j < 4; j++)
#pragma unroll
            for (int q = 0; q < 4; q++) c[i][j][q] = 0.f;

    gram_load(sb, pAh, pAl, pBh, pBl, 0, tid);
    CP_COMMIT();

    const int NIT = MDIM / 64;   // 256
    for (int it = 0; it < NIT; ++it) {
        const int s = it & 1;
        if (it + 1 < NIT) {
            gram_load(sb + (s ^ 1) * G_STAGE, pAh, pAl, pBh, pBl, (it + 1) * 64, tid);
            CP_COMMIT();
            CP_WAIT(1);
        } else {
            CP_WAIT(0);
        }
        __syncthreads();
        const uint32_t st = sb + s * G_STAGE;

#pragma unroll
        for (int ks = 0; ks < 4; ks++) {
            uint32_t aH[4][4], aL[4][4], bH[4][2], bL[4][2];
            const int mrowA = ks * 16 + ((l & 16) >> 1) + (l & 7);
            const uint32_t abase = st + mrowA * G_LDA + (wd * 64 + (l & 8)) * 2;
#pragma unroll
            for (int ma = 0; ma < 4; ma++) {
                uint32_t ad = abase + ma * 32;
                ldsm4t(aH[ma], ad);
                ldsm4t(aL[ma], ad + G_TILE);
            }
            const int mrowB = ks * 16 + (l & 15);
            const uint32_t bbase = st + 2 * G_TILE + mrowB * G_LDA + (we * 32) * 2;
#pragma unroll
            for (int na = 0; na < 4; na++) {
                uint32_t bd = bbase + na * 16;
                ldsm2t(bH[na], bd);
                ldsm2t(bL[na], bd + G_TILE);
            }
#pragma unroll
            for (int ma = 0; ma < 4; ma++)
#pragma unroll
                for (int na = 0; na < 4; na++) {
                    mma_bf16(c[ma][na], aH[ma], bH[na]);
                    mma_bf16(c[ma][na], aH[ma], bL[na]);
                    mma_bf16(c[ma][na], aL[ma], bH[na]);
                }
        }
        __syncthreads();
    }

    float* G = g_energy + (size_t)b * DDIM * DDIM;
#pragma unroll
    for (int ma = 0; ma < 4; ma++) {
        const int row0 = d0 + wd * 64 + ma * 16 + (l >> 2);
#pragma unroll
        for (int na = 0; na < 4; na++) {
            const int col = e0 + we * 32 + na * 8 + (l & 3) * 2;
            *reinterpret_cast<float2*>(G + (size_t)row0 * DDIM + col) =
                make_float2(c[ma][na][0], c[ma][na][1]);
            *reinterpret_cast<float2*>(G + (size_t)(row0 + 8) * DDIM + col) =
                make_float2(c[ma][na][2], c[ma][na][3]);
        }
    }
}

// ---------------------------------------------------------------------------
// Kernel 2: softmax(-G) per row -> att hi/lo bf16 ([d][e] layout)
// ---------------------------------------------------------------------------
__global__ void softmax_kernel() {
    const int b = blockIdx.y;
    const int d = blockIdx.x;
    const float* Grow = g_energy + (size_t)b * DDIM * DDIM + (size_t)d * DDIM;
    __nv_bfloat16* Ah = g_att_hi + (size_t)b * DDIM * DDIM + (size_t)d * DDIM;
    __nv_bfloat16* Al = g_att_lo + (size_t)b * DDIM * DDIM + (size_t)d * DDIM;

    __shared__ float red[256];
    const int t = threadIdx.x;
    float v0 = Grow[t], v1 = Grow[t + 256];

    red[t] = fminf(v0, v1);
    __syncthreads();
#pragma unroll
    for (int s = 128; s > 0; s >>= 1) {
        if (t < s) red[t] = fminf(red[t], red[t + s]);
        __syncthreads();
    }
    const float gmin = red[0];
    __syncthreads();

    float p0 = expf(gmin - v0);
    float p1 = expf(gmin - v1);
    red[t] = p0 + p1;
    __syncthreads();
#pragma unroll
    for (int s = 128; s > 0; s >>= 1) {
        if (t < s) red[t] += red[t + s];
        __syncthreads();
    }
    const float inv = 1.f / red[0];
    p0 *= inv; p1 *= inv;

    __nv_bfloat16 h0 = __float2bfloat16(p0);
    __nv_bfloat16 h1 = __float2bfloat16(p1);
    Ah[t] = h0;
    Ah[t + 256] = h1;
    Al[t] = __float2bfloat16(p0 - __bfloat162float(h0));
    Al[t + 256] = __float2bfloat16(p1 - __bfloat162float(h1));
}

// ---------------------------------------------------------------------------
// Kernel 3: Y = gamma * (X @ Att^T) + X via mma.sync
// out[m, d] = sum_e X[m,e] * Att[d,e].  CTA tile 128(m)x128(d), BK=64 over e.
// Smem tiles: [128 rows][64 k + 8 pad] bf16, row stride 144B.
// ---------------------------------------------------------------------------
#define Q_LDA   144
#define Q_TILE  (128 * Q_LDA)     // 18432
#define Q_STAGE (4 * Q_TILE)      // 73728
#define Q_SMEM  (2 * Q_STAGE)     // 147456

__device__ __forceinline__ void g2_load(uint32_t dst, const char* Ah, const char* Al,
                                        const char* Bh, const char* Bl, int k0, int tid) {
    const char* srcs[4] = {Ah, Al, Bh, Bl};
#pragma unroll
    for (int t = 0; t < 4; t++) {
        uint32_t db = dst + t * Q_TILE;
        const char* sp = srcs[t] + k0 * 2;
#pragma unroll
        for (int j = 0; j < 4; j++) {
            int idx = tid + j * 256;
            int row = idx >> 3, c16 = idx & 7;
            cp16(db + row * Q_LDA + c16 * 16, sp + (size_t)row * 1024 + c16 * 16);
        }
    }
}

__global__ __launch_bounds__(256, 1) void gemm2_mma_kernel(const float* __restrict__ x,
                                                           const float* __restrict__ gam,
                                                           float* __restrict__ out) {
    const uint32_t sb = smem_u32(dyn_smem);
    const int tid = threadIdx.x, l = tid & 31, w = tid >> 5;
    const int wm = w & 1, wn = w >> 1;            // warp tile: 64 (m) x 32 (d)
    const int b = blockIdx.z, d0 = blockIdx.x * 128, m0 = blockIdx.y * 128;

    const char* Ah = (const char*)(g_x_hi + (size_t)b * MDIM * DDIM + (size_t)m0 * DDIM);
    const char* Al = (const char*)(g_x_lo + (size_t)b * MDIM * DDIM + (size_t)m0 * DDIM);
    const char* Bh = (const char*)(g_att_hi + (size_t)b * DDIM * DDIM + (size_t)d0 * DDIM);
    const char* Bl = (const char*)(g_att_lo + (size_t)b * DDIM * DDIM + (size_t)d0 * DDIM);

    float c[4][4][4];
#pragma unroll
    for (int i = 0; i < 4; i++)
#pragma unroll
        for (int j = 0; j < 4; j++)
#pragma unroll
            for (int q = 0; q < 4; q++) c[i][j][q] = 0.f;

    g2_load(sb, Ah, Al, Bh, Bl, 0, tid);
    CP_COMMIT();

    const int NIT = DDIM / 64;    // 8
    for (int it = 0; it < NIT; ++it) {
        const int s = it & 1;
        if (it + 1 < NIT) {
            g2_load(sb + (s ^ 1) * Q_STAGE, Ah, Al, Bh, Bl, (it + 1) * 64, tid);
            CP_COMMIT();
            CP_WAIT(1);
        } else {
            CP_WAIT(0);
        }
        __syncthreads();
        const uint32_t st = sb + s * Q_STAGE;

#pragma unroll
        for (int ks = 0; ks < 4; ks++) {
            uint32_t aH[4][4], aL[4][4], bH[4][2], bL[4][2];
            const uint32_t akb = (ks * 16 + (l >> 4) * 8) * 2;
#pragma unroll
            for (int ma = 0; ma < 4; ma++) {
                const int arow = wm * 64 + ma * 16 + (l & 15);
                uint32_t ad = st + arow * Q_LDA + akb;
                ldsm4(aH[ma], ad);
                ldsm4(aL[ma], ad + Q_TILE);
            }
            const uint32_t bkb = (ks * 16 + ((l >> 3) & 1) * 8) * 2;
#pragma unroll
            for (int na = 0; na < 4; na++) {
                const int brow = wn * 32 + na * 8 + (l & 7);
                uint32_t bd = st + 2 * Q_TILE + brow * Q_LDA + bkb;
                ldsm2(bH[na], bd);
                ldsm2(bL[na], bd + Q_TILE);
            }
#pragma unroll
            for (int ma = 0; ma < 4; ma++)
#pragma unroll
                for (int na = 0; na < 4; na++) {
                    mma_bf16(c[ma][na], aH[ma], bH[na]);
                    mma_bf16(c[ma][na], aH[ma], bL[na]);
                    mma_bf16(c[ma][na], aL[ma], bH[na]);
                }
        }
        __syncthreads();
    }

    const float gv = gam[0];
    const float* X = x + (size_t)b * MDIM * DDIM;
    float* Y = out + (size_t)b * MDIM * DDIM;
#pragma unroll
    for (int ma = 0; ma < 4; ma++) {
        const int row0 = m0 + wm * 64 + ma * 16 + (l >> 2);
#pragma unroll
        for (int na = 0; na < 4; na++) {
            const int col = d0 + wn * 32 + na * 8 + (l & 3) * 2;
            {
                float2 xv = *reinterpret_cast<const float2*>(X + (size_t)row0 * DDIM + col);
                *reinterpret_cast<float2*>(Y + (size_t)row0 * DDIM + col) =
                    make_float2(gv * c[ma][na][0] + xv.x, gv * c[ma][na][1] + xv.y);
            }
            {
                float2 xv = *reinterpret_cast<const float2*>(X + (size_t)(row0 + 8) * DDIM + col);
                *reinterpret_cast<float2*>(Y + (size_t)(row0 + 8) * DDIM + col) =
                    make_float2(gv * c[ma][na][2] + xv.x, gv * c[ma][na][3] + xv.y);
            }
        }
    }
}

// ---------------------------------------------------------------------------
extern "C" void kernel_launch(void* const* d_in, const int* in_sizes, int n_in,
                              void* d_out, int out_size) {
    const float* x     = (const float*)d_in[0];
    const float* gamma = (const float*)d_in[1];
    float* out = (float*)d_out;

    cudaFuncSetAttribute(gram_mma_kernel, cudaFuncAttributeMaxDynamicSharedMemorySize, G_SMEM);
    cudaFuncSetAttribute(gemm2_mma_kernel, cudaFuncAttributeMaxDynamicSharedMemorySize, Q_SMEM);

    split_kernel<<<4096, 256>>>(x);
    gram_mma_kernel<<<dim3(4, 4, BATCH), 256, G_SMEM>>>();
    softmax_kernel<<<dim3(DDIM, BATCH), 256>>>();
    gemm2_mma_kernel<<<dim3(4, MDIM / 128, BATCH), 256, Q_SMEM>>>(x, gamma, out);
}

// round 6
// speedup vs baseline: 3.2149x; 1.1459x over previous
#include <cuda_runtime.h>
#include <cuda_bf16.h>
#include <cstdint>
#include <math.h>

#define BATCH 8
#define MDIM  16384
#define DDIM  512

// ---------------- scratch (device globals; no allocations allowed) ----------
__device__ __nv_bfloat16 g_x_hi[(size_t)BATCH * MDIM * DDIM];    // X hi (128MB)
__device__ __nv_bfloat16 g_x_lo[(size_t)BATCH * MDIM * DDIM];    // X lo (128MB)
__device__ float         g_energy[(size_t)BATCH * DDIM * DDIM];  // G    (8MB)
__device__ __nv_bfloat16 g_att_hi[(size_t)BATCH * DDIM * DDIM];  // A hi (4MB)
__device__ __nv_bfloat16 g_att_lo[(size_t)BATCH * DDIM * DDIM];  // A lo (4MB)

// ---------------- helpers ----------------
__device__ __forceinline__ uint32_t smem_u32(const void* p) {
    uint32_t a;
    asm("{ .reg .u64 t; cvta.to.shared.u64 t, %1; cvt.u32.u64 %0, t; }" : "=r"(a) : "l"(p));
    return a;
}
__device__ __forceinline__ void cp16(uint32_t dst, const void* src) {
    asm volatile("cp.async.cg.shared.global [%0], [%1], 16;" :: "r"(dst), "l"(src));
}
#define CP_COMMIT() asm volatile("cp.async.commit_group;" ::: "memory")
#define CP_WAIT(n)  asm volatile("cp.async.wait_group %0;" :: "n"(n) : "memory")

__device__ __forceinline__ void mma_bf16(float* c, const uint32_t* a, const uint32_t* b) {
    asm volatile(
        "mma.sync.aligned.m16n8k16.row.col.f32.bf16.bf16.f32 "
        "{%0,%1,%2,%3}, {%4,%5,%6,%7}, {%8,%9}, {%0,%1,%2,%3};"
        : "+f"(c[0]), "+f"(c[1]), "+f"(c[2]), "+f"(c[3])
        : "r"(a[0]), "r"(a[1]), "r"(a[2]), "r"(a[3]), "r"(b[0]), "r"(b[1]));
}
__device__ __forceinline__ void ldsm4(uint32_t* r, uint32_t a) {
    asm volatile("ldmatrix.sync.aligned.m8n8.x4.shared.b16 {%0,%1,%2,%3}, [%4];"
                 : "=r"(r[0]), "=r"(r[1]), "=r"(r[2]), "=r"(r[3]) : "r"(a));
}
__device__ __forceinline__ void ldsm4t(uint32_t* r, uint32_t a) {
    asm volatile("ldmatrix.sync.aligned.m8n8.x4.trans.shared.b16 {%0,%1,%2,%3}, [%4];"
                 : "=r"(r[0]), "=r"(r[1]), "=r"(r[2]), "=r"(r[3]) : "r"(a));
}
__device__ __forceinline__ void ldsm2(uint32_t* r, uint32_t a) {
    asm volatile("ldmatrix.sync.aligned.m8n8.x2.shared.b16 {%0,%1}, [%2];"
                 : "=r"(r[0]), "=r"(r[1]) : "r"(a));
}
__device__ __forceinline__ void ldsm2t(uint32_t* r, uint32_t a) {
    asm volatile("ldmatrix.sync.aligned.m8n8.x2.trans.shared.b16 {%0,%1}, [%2];"
                 : "=r"(r[0]), "=r"(r[1]) : "r"(a));
}

// ---------------------------------------------------------------------------
// Kernel Z: zero g_energy (atomic accumulation target; must be cleared per run)
// ---------------------------------------------------------------------------
__global__ void zero_energy_kernel() {
    const size_t n4 = (size_t)BATCH * DDIM * DDIM / 4;
    const size_t stride = (size_t)gridDim.x * blockDim.x;
    for (size_t i = (size_t)blockIdx.x * blockDim.x + threadIdx.x; i < n4; i += stride)
        reinterpret_cast<float4*>(g_energy)[i] = make_float4(0.f, 0.f, 0.f, 0.f);
}

// ---------------------------------------------------------------------------
// Kernel 0: bf16 hi/lo split of x (natural [m, d] layout)
// ---------------------------------------------------------------------------
__global__ void split_kernel(const float* __restrict__ x) {
    const size_t n4 = (size_t)BATCH * MDIM * DDIM / 4;
    const size_t stride = (size_t)gridDim.x * blockDim.x;
    for (size_t i = (size_t)blockIdx.x * blockDim.x + threadIdx.x; i < n4; i += stride) {
        float4 v = reinterpret_cast<const float4*>(x)[i];
        __nv_bfloat16 h0 = __float2bfloat16(v.x), h1 = __float2bfloat16(v.y);
        __nv_bfloat16 h2 = __float2bfloat16(v.z), h3 = __float2bfloat16(v.w);
        __nv_bfloat16 l0 = __float2bfloat16(v.x - __bfloat162float(h0));
        __nv_bfloat16 l1 = __float2bfloat16(v.y - __bfloat162float(h1));
        __nv_bfloat16 l2 = __float2bfloat16(v.z - __bfloat162float(h2));
        __nv_bfloat16 l3 = __float2bfloat16(v.w - __bfloat162float(h3));
        uint2 hw, lw;
        hw.x = ((uint32_t)__bfloat16_as_ushort(h1) << 16) | __bfloat16_as_ushort(h0);
        hw.y = ((uint32_t)__bfloat16_as_ushort(h3) << 16) | __bfloat16_as_ushort(h2);
        lw.x = ((uint32_t)__bfloat16_as_ushort(l1) << 16) | __bfloat16_as_ushort(l0);
        lw.y = ((uint32_t)__bfloat16_as_ushort(l3) << 16) | __bfloat16_as_ushort(l2);
        reinterpret_cast<uint2*>(g_x_hi)[i] = hw;
        reinterpret_cast<uint2*>(g_x_lo)[i] = lw;
    }
}

// ---------------------------------------------------------------------------
// Kernel 1: Gram via mma.sync, symmetric-pair + K-split-8 decomposition.
// G[d,e] = sum_m X[m,d]*X[m,e].  CTA computes 128x128 tile (pair p) for
// m in [ky*2048, (ky+1)*2048), atomically accumulates into g_energy
// (and the transposed tile for off-diagonal pairs).
// 512 threads, 16 warps (4x4), warp tile 32x32. BK=64 over m, double buffer.
// Smem panel: [64 m-rows][128 cols + 8 pad] bf16, row stride 272B.
// ---------------------------------------------------------------------------
#define G_LDA   272
#define G_TILE  (64 * G_LDA)      // 17408
#define G_STAGE (4 * G_TILE)      // 69632
#define G_SMEM  (2 * G_STAGE)     // 139264
#define KSPLIT  8
#define MCHUNK  (MDIM / KSPLIT)   // 2048

__constant__ int c_pair_ti[10] = {0,0,0,0,1,1,1,2,2,3};
__constant__ int c_pair_tj[10] = {0,1,2,3,1,2,3,2,3,3};

__device__ __forceinline__ void gram_load(uint32_t dst, const char* Ah, const char* Al,
                                          const char* Bh, const char* Bl, int m0, int tid) {
    const char* srcs[4] = {Ah, Al, Bh, Bl};
#pragma unroll
    for (int t = 0; t < 4; t++) {
        uint32_t db = dst + t * G_TILE;
        const char* sp = srcs[t] + (size_t)m0 * 1024;
#pragma unroll
        for (int j = 0; j < 2; j++) {
            int idx = tid + j * 512;
            int row = idx >> 4, c16 = idx & 15;
            cp16(db + row * G_LDA + c16 * 16, sp + (size_t)row * 1024 + c16 * 16);
        }
    }
}

extern __shared__ char dyn_smem[];

__global__ __launch_bounds__(512, 1) void gram_mma_kernel() {
    const uint32_t sb = smem_u32(dyn_smem);
    const int tid = threadIdx.x, l = tid & 31, w = tid >> 5;
    const int wm = w & 3, wn = w >> 2;            // warp tile: 32 (d) x 32 (e)
    const int b = blockIdx.z;
    const int ti = c_pair_ti[blockIdx.x], tj = c_pair_tj[blockIdx.x];
    const int d0 = ti * 128, e0 = tj * 128;
    const int mbase = blockIdx.y * MCHUNK;

    const char* xh = (const char*)(g_x_hi + (size_t)b * MDIM * DDIM) + (size_t)mbase * 1024;
    const char* xl = (const char*)(g_x_lo + (size_t)b * MDIM * DDIM) + (size_t)mbase * 1024;
    const char* pAh = xh + d0 * 2;
    const char* pAl = xl + d0 * 2;
    const char* pBh = xh + e0 * 2;
    const char* pBl = xl + e0 * 2;

    float c[2][4][4];
#pragma unroll
    for (int i = 0; i < 2; i++)
#pragma unroll
        for (int j = 0; j < 4; j++)
#pragma unroll
            for (int q = 0; q < 4; q++) c[i][j][q] = 0.f;

    gram_load(sb, pAh, pAl, pBh, pBl, 0, tid);
    CP_COMMIT();

    const int NIT = MCHUNK / 64;   // 32
    for (int it = 0; it < NIT; ++it) {
        const int s = it & 1;
        if (it + 1 < NIT) {
            gram_load(sb + (s ^ 1) * G_STAGE, pAh, pAl, pBh, pBl, (it + 1) * 64, tid);
            CP_COMMIT();
            CP_WAIT(1);
        } else {
            CP_WAIT(0);
        }
        __syncthreads();
        const uint32_t st = sb + s * G_STAGE;

#pragma unroll
        for (int ks = 0; ks < 4; ks++) {
            uint32_t aH[2][4], aL[2][4], bH[4][2], bL[4][2];
            const int mrowA = ks * 16 + ((l & 16) >> 1) + (l & 7);
            const uint32_t abase = st + mrowA * G_LDA + (wm * 32 + (l & 8)) * 2;
#pragma unroll
            for (int ma = 0; ma < 2; ma++) {
                uint32_t ad = abase + ma * 32;
                ldsm4t(aH[ma], ad);
                ldsm4t(aL[ma], ad + G_TILE);
            }
            const int mrowB = ks * 16 + (l & 15);
            const uint32_t bbase = st + 2 * G_TILE + mrowB * G_LDA + (wn * 32) * 2;
#pragma unroll
            for (int na = 0; na < 4; na++) {
                uint32_t bd = bbase + na * 16;
                ldsm2t(bH[na], bd);
                ldsm2t(bL[na], bd + G_TILE);
            }
#pragma unroll
            for (int ma = 0; ma < 2; ma++)
#pragma unroll
                for (int na = 0; na < 4; na++) {
                    mma_bf16(c[ma][na], aH[ma], bH[na]);
                    mma_bf16(c[ma][na], aH[ma], bL[na]);
                    mma_bf16(c[ma][na], aL[ma], bH[na]);
                }
        }
        __syncthreads();
    }

    float* G = g_energy + (size_t)b * DDIM * DDIM;
    const bool offdiag = (ti != tj);
#pragma unroll
    for (int ma = 0; ma < 2; ma++) {
        const int row0 = d0 + wm * 32 + ma * 16 + (l >> 2);
#pragma unroll
        for (int na = 0; na < 4; na++) {
            const int col = e0 + wn * 32 + na * 8 + (l & 3) * 2;
            atomicAdd(&G[(size_t)row0 * DDIM + col],       c[ma][na][0]);
            atomicAdd(&G[(size_t)row0 * DDIM + col + 1],   c[ma][na][1]);
            atomicAdd(&G[(size_t)(row0 + 8) * DDIM + col],     c[ma][na][2]);
            atomicAdd(&G[(size_t)(row0 + 8) * DDIM + col + 1], c[ma][na][3]);
            if (offdiag) {
                atomicAdd(&G[(size_t)col * DDIM + row0],           c[ma][na][0]);
                atomicAdd(&G[(size_t)(col + 1) * DDIM + row0],     c[ma][na][1]);
                atomicAdd(&G[(size_t)col * DDIM + row0 + 8],       c[ma][na][2]);
                atomicAdd(&G[(size_t)(col + 1) * DDIM + row0 + 8], c[ma][na][3]);
            }
        }
    }
}

// ---------------------------------------------------------------------------
// Kernel 2: softmax(-G) per row -> att hi/lo bf16 ([d][e] layout)
// ---------------------------------------------------------------------------
__global__ void softmax_kernel() {
    const int b = blockIdx.y;
    const int d = blockIdx.x;
    const float* Grow = g_energy + (size_t)b * DDIM * DDIM + (size_t)d * DDIM;
    __nv_bfloat16* Ah = g_att_hi + (size_t)b * DDIM * DDIM + (size_t)d * DDIM;
    __nv_bfloat16* Al = g_att_lo + (size_t)b * DDIM * DDIM + (size_t)d * DDIM;

    __shared__ float red[256];
    const int t = threadIdx.x;
    float v0 = Grow[t], v1 = Grow[t + 256];

    red[t] = fminf(v0, v1);
    __syncthreads();
#pragma unroll
    for (int s = 128; s > 0; s >>= 1) {
        if (t < s) red[t] = fminf(red[t], red[t + s]);
        __syncthreads();
    }
    const float gmin = red[0];
    __syncthreads();

    float p0 = expf(gmin - v0);
    float p1 = expf(gmin - v1);
    red[t] = p0 + p1;
    __syncthreads();
#pragma unroll
    for (int s = 128; s > 0; s >>= 1) {
        if (t < s) red[t] += red[t + s];
        __syncthreads();
    }
    const float inv = 1.f / red[0];
    p0 *= inv; p1 *= inv;

    __nv_bfloat16 h0 = __float2bfloat16(p0);
    __nv_bfloat16 h1 = __float2bfloat16(p1);
    Ah[t] = h0;
    Ah[t + 256] = h1;
    Al[t] = __float2bfloat16(p0 - __bfloat162float(h0));
    Al[t + 256] = __float2bfloat16(p1 - __bfloat162float(h1));
}

// ---------------------------------------------------------------------------
// Kernel 3: Y = gamma * (X @ Att^T) + X via mma.sync
// out[m, d] = sum_e X[m,e] * Att[d,e].  CTA tile 128(m)x128(d), BK=64 over e.
// 512 threads, 16 warps (4x4), warp tile 32x32.
// Smem tiles: [128 rows][64 k + 8 pad] bf16, row stride 144B.
// ---------------------------------------------------------------------------
#define Q_LDA   144
#define Q_TILE  (128 * Q_LDA)     // 18432
#define Q_STAGE (4 * Q_TILE)      // 73728
#define Q_SMEM  (2 * Q_STAGE)     // 147456

__device__ __forceinline__ void g2_load(uint32_t dst, const char* Ah, const char* Al,
                                        const char* Bh, const char* Bl, int k0, int tid) {
    const char* srcs[4] = {Ah, Al, Bh, Bl};
#pragma unroll
    for (int t = 0; t < 4; t++) {
        uint32_t db = dst + t * Q_TILE;
        const char* sp = srcs[t] + k0 * 2;
#pragma unroll
        for (int j = 0; j < 2; j++) {
            int idx = tid + j * 512;
            int row = idx >> 3, c16 = idx & 7;
            cp16(db + row * Q_LDA + c16 * 16, sp + (size_t)row * 1024 + c16 * 16);
        }
    }
}

__global__ __launch_bounds__(512, 1) void gemm2_mma_kernel(const float* __restrict__ x,
                                                           const float* __restrict__ gam,
                                                           float* __restrict__ out) {
    const uint32_t sb = smem_u32(dyn_smem);
    const int tid = threadIdx.x, l = tid & 31, w = tid >> 5;
    const int wm = w & 3, wn = w >> 2;            // warp tile: 32 (m) x 32 (d)
    const int b = blockIdx.z, d0 = blockIdx.x * 128, m0 = blockIdx.y * 128;

    const char* Ah = (const char*)(g_x_hi + (size_t)b * MDIM * DDIM + (size_t)m0 * DDIM);
    const char* Al = (const char*)(g_x_lo + (size_t)b * MDIM * DDIM + (size_t)m0 * DDIM);
    const char* Bh = (const char*)(g_att_hi + (size_t)b * DDIM * DDIM + (size_t)d0 * DDIM);
    const char* Bl = (const char*)(g_att_lo + (size_t)b * DDIM * DDIM + (size_t)d0 * DDIM);

    float c[2][4][4];
#pragma unroll
    for (int i = 0; i < 2; i++)
#pragma unroll
        for (int j = 0; j < 4; j++)
#pragma unroll
            for (int q = 0; q < 4; q++) c[i][j][q] = 0.f;

    g2_load(sb, Ah, Al, Bh, Bl, 0, tid);
    CP_COMMIT();

    const int NIT = DDIM / 64;    // 8
    for (int it = 0; it < NIT; ++it) {
        const int s = it & 1;
        if (it + 1 < NIT) {
            g2_load(sb + (s ^ 1) * Q_STAGE, Ah, Al, Bh, Bl, (it + 1) * 64, tid);
            CP_COMMIT();
            CP_WAIT(1);
        } else {
            CP_WAIT(0);
        }
        __syncthreads();
        const uint32_t st = sb + s * Q_STAGE;

#pragma unroll
        for (int ks = 0; ks < 4; ks++) {
            uint32_t aH[2][4], aL[2][4], bH[4][2], bL[4][2];
            const uint32_t akb = (ks * 16 + (l >> 4) * 8) * 2;
#pragma unroll
            for (int ma = 0; ma < 2; ma++) {
                const int arow = wm * 32 + ma * 16 + (l & 15);
                uint32_t ad = st + arow * Q_LDA + akb;
                ldsm4(aH[ma], ad);
                ldsm4(aL[ma], ad + Q_TILE);
            }
            const uint32_t bkb = (ks * 16 + ((l >> 3) & 1) * 8) * 2;
#pragma unroll
            for (int na = 0; na < 4; na++) {
                const int brow = wn * 32 + na * 8 + (l & 7);
                uint32_t bd = st + 2 * Q_TILE + brow * Q_LDA + bkb;
                ldsm2(bH[na], bd);
                ldsm2(bL[na], bd + Q_TILE);
            }
#pragma unroll
            for (int ma = 0; ma < 2; ma++)
#pragma unroll
                for (int na = 0; na < 4; na++) {
                    mma_bf16(c[ma][na], aH[ma], bH[na]);
                    mma_bf16(c[ma][na], aH[ma], bL[na]);
                    mma_bf16(c[ma][na], aL[ma], bH[na]);
                }
        }
        __syncthreads();
    }

    const float gv = gam[0];
    const float* X = x + (size_t)b * MDIM * DDIM;
    float* Y = out + (size_t)b * MDIM * DDIM;
#pragma unroll
    for (int ma = 0; ma < 2; ma++) {
        const int row0 = m0 + wm * 32 + ma * 16 + (l >> 2);
#pragma unroll
        for (int na = 0; na < 4; na++) {
            const int col = d0 + wn * 32 + na * 8 + (l & 3) * 2;
            {
                float2 xv = *reinterpret_cast<const float2*>(X + (size_t)row0 * DDIM + col);
                *reinterpret_cast<float2*>(Y + (size_t)row0 * DDIM + col) =
                    make_float2(gv * c[ma][na][0] + xv.x, gv * c[ma][na][1] + xv.y);
            }
            {
                float2 xv = *reinterpret_cast<const float2*>(X + (size_t)(row0 + 8) * DDIM + col);
                *reinterpret_cast<float2*>(Y + (size_t)(row0 + 8) * DDIM + col) =
                    make_float2(gv * c[ma][na][2] + xv.x, gv * c[ma][na][3] + xv.y);
            }
        }
    }
}

// ---------------------------------------------------------------------------
extern "C" void kernel_launch(void* const* d_in, const int* in_sizes, int n_in,
                              void* d_out, int out_size) {
    const float* x     = (const float*)d_in[0];
    const float* gamma = (const float*)d_in[1];
    float* out = (float*)d_out;

    cudaFuncSetAttribute(gram_mma_kernel, cudaFuncAttributeMaxDynamicSharedMemorySize, G_SMEM);
    cudaFuncSetAttribute(gemm2_mma_kernel, cudaFuncAttributeMaxDynamicSharedMemorySize, Q_SMEM);

    zero_energy_kernel<<<1024, 256>>>();
    split_kernel<<<4096, 256>>>(x);
    gram_mma_kernel<<<dim3(10, KSPLIT, BATCH), 512, G_SMEM>>>();
    softmax_kernel<<<dim3(DDIM, BATCH), 256>>>();
    gemm2_mma_kernel<<<dim3(4, MDIM / 128, BATCH), 512, Q_SMEM>>>(x, gamma, out);
}

// round 7
// speedup vs baseline: 3.6956x; 1.1495x over previous
#include <cuda_runtime.h>
#include <cuda_fp16.h>
#include <cstdint>
#include <math.h>

#define BATCH 8
#define MDIM  16384
#define DDIM  512

// ---------------- scratch (device globals; no allocations allowed) ----------
__device__ __half g_x_hi[(size_t)BATCH * MDIM * DDIM];    // X hi (128MB)
__device__ __half g_x_lo[(size_t)BATCH * MDIM * DDIM];    // X lo (128MB)
__device__ float  g_energy[(size_t)BATCH * DDIM * DDIM];  // G    (8MB)
__device__ __half g_att[(size_t)BATCH * DDIM * DDIM];     // A    (4MB)

// ---------------- helpers ----------------
__device__ __forceinline__ uint32_t smem_u32(const void* p) {
    uint32_t a;
    asm("{ .reg .u64 t; cvta.to.shared.u64 t, %1; cvt.u32.u64 %0, t; }" : "=r"(a) : "l"(p));
    return a;
}
__device__ __forceinline__ void cp16(uint32_t dst, const void* src) {
    asm volatile("cp.async.cg.shared.global [%0], [%1], 16;" :: "r"(dst), "l"(src));
}
#define CP_COMMIT() asm volatile("cp.async.commit_group;" ::: "memory")
#define CP_WAIT(n)  asm volatile("cp.async.wait_group %0;" :: "n"(n) : "memory")

__device__ __forceinline__ void mma_f16(float* c, const uint32_t* a, const uint32_t* b) {
    asm volatile(
        "mma.sync.aligned.m16n8k16.row.col.f32.f16.f16.f32 "
        "{%0,%1,%2,%3}, {%4,%5,%6,%7}, {%8,%9}, {%0,%1,%2,%3};"
        : "+f"(c[0]), "+f"(c[1]), "+f"(c[2]), "+f"(c[3])
        : "r"(a[0]), "r"(a[1]), "r"(a[2]), "r"(a[3]), "r"(b[0]), "r"(b[1]));
}
__device__ __forceinline__ void ldsm4(uint32_t* r, uint32_t a) {
    asm volatile("ldmatrix.sync.aligned.m8n8.x4.shared.b16 {%0,%1,%2,%3}, [%4];"
                 : "=r"(r[0]), "=r"(r[1]), "=r"(r[2]), "=r"(r[3]) : "r"(a));
}
__device__ __forceinline__ void ldsm4t(uint32_t* r, uint32_t a) {
    asm volatile("ldmatrix.sync.aligned.m8n8.x4.trans.shared.b16 {%0,%1,%2,%3}, [%4];"
                 : "=r"(r[0]), "=r"(r[1]), "=r"(r[2]), "=r"(r[3]) : "r"(a));
}
__device__ __forceinline__ void ldsm2(uint32_t* r, uint32_t a) {
    asm volatile("ldmatrix.sync.aligned.m8n8.x2.shared.b16 {%0,%1}, [%2];"
                 : "=r"(r[0]), "=r"(r[1]) : "r"(a));
}
__device__ __forceinline__ void ldsm2t(uint32_t* r, uint32_t a) {
    asm volatile("ldmatrix.sync.aligned.m8n8.x2.trans.shared.b16 {%0,%1}, [%2];"
                 : "=r"(r[0]), "=r"(r[1]) : "r"(a));
}

// ---------------------------------------------------------------------------
// Kernel Z: zero g_energy (atomic accumulation target)
// ---------------------------------------------------------------------------
__global__ void zero_energy_kernel() {
    const size_t n4 = (size_t)BATCH * DDIM * DDIM / 4;
    const size_t stride = (size_t)gridDim.x * blockDim.x;
    for (size_t i = (size_t)blockIdx.x * blockDim.x + threadIdx.x; i < n4; i += stride)
        reinterpret_cast<float4*>(g_energy)[i] = make_float4(0.f, 0.f, 0.f, 0.f);
}

// ---------------------------------------------------------------------------
// Kernel 0: fp16 hi/lo split of x (natural [m, d] layout)
// ---------------------------------------------------------------------------
__global__ void split_kernel(const float* __restrict__ x) {
    const size_t n4 = (size_t)BATCH * MDIM * DDIM / 4;
    const size_t stride = (size_t)gridDim.x * blockDim.x;
    for (size_t i = (size_t)blockIdx.x * blockDim.x + threadIdx.x; i < n4; i += stride) {
        float4 v = reinterpret_cast<const float4*>(x)[i];
        __half h0 = __float2half_rn(v.x), h1 = __float2half_rn(v.y);
        __half h2 = __float2half_rn(v.z), h3 = __float2half_rn(v.w);
        __half l0 = __float2half_rn(v.x - __half2float(h0));
        __half l1 = __float2half_rn(v.y - __half2float(h1));
        __half l2 = __float2half_rn(v.z - __half2float(h2));
        __half l3 = __float2half_rn(v.w - __half2float(h3));
        uint2 hw, lw;
        hw.x = ((uint32_t)__half_as_ushort(h1) << 16) | __half_as_ushort(h0);
        hw.y = ((uint32_t)__half_as_ushort(h3) << 16) | __half_as_ushort(h2);
        lw.x = ((uint32_t)__half_as_ushort(l1) << 16) | __half_as_ushort(l0);
        lw.y = ((uint32_t)__half_as_ushort(l3) << 16) | __half_as_ushort(l2);
        reinterpret_cast<uint2*>(g_x_hi)[i] = hw;
        reinterpret_cast<uint2*>(g_x_lo)[i] = lw;
    }
}

// ---------------------------------------------------------------------------
// Kernel 1: Gram via mma.sync, symmetric pairs + K-split-8, 3-stage pipeline.
// G[d,e] = sum_m X[m,d]*X[m,e].  512 threads, warp tile 32x32.
// Smem panel: [64 m-rows][128 cols + 8 pad] fp16, row stride 272B.
// ---------------------------------------------------------------------------
#define G_LDA   272
#define G_TILE  (64 * G_LDA)      // 17408
#define G_STAGE (4 * G_TILE)      // 69632
#define G_SMEM  (3 * G_STAGE)     // 208896
#define KSPLIT  8
#define MCHUNK  (MDIM / KSPLIT)   // 2048

__constant__ int c_pair_ti[10] = {0,0,0,0,1,1,1,2,2,3};
__constant__ int c_pair_tj[10] = {0,1,2,3,1,2,3,2,3,3};

__device__ __forceinline__ void gram_load(uint32_t dst, const char* Ah, const char* Al,
                                          const char* Bh, const char* Bl, int m0, int tid) {
    const char* srcs[4] = {Ah, Al, Bh, Bl};
#pragma unroll
    for (int t = 0; t < 4; t++) {
        uint32_t db = dst + t * G_TILE;
        const char* sp = srcs[t] + (size_t)m0 * 1024;
#pragma unroll
        for (int j = 0; j < 2; j++) {
            int idx = tid + j * 512;
            int row = idx >> 4, c16 = idx & 15;
            cp16(db + row * G_LDA + c16 * 16, sp + (size_t)row * 1024 + c16 * 16);
        }
    }
}

extern __shared__ char dyn_smem[];

__global__ __launch_bounds__(512, 1) void gram_mma_kernel() {
    const uint32_t sb = smem_u32(dyn_smem);
    const int tid = threadIdx.x, l = tid & 31, w = tid >> 5;
    const int wm = w & 3, wn = w >> 2;            // warp tile: 32 (d) x 32 (e)
    const int b = blockIdx.z;
    const int ti = c_pair_ti[blockIdx.x], tj = c_pair_tj[blockIdx.x];
    const int d0 = ti * 128, e0 = tj * 128;
    const int mbase = blockIdx.y * MCHUNK;

    const char* xh = (const char*)(g_x_hi + (size_t)b * MDIM * DDIM) + (size_t)mbase * 1024;
    const char* xl = (const char*)(g_x_lo + (size_t)b * MDIM * DDIM) + (size_t)mbase * 1024;
    const char* pAh = xh + d0 * 2;
    const char* pAl = xl + d0 * 2;
    const char* pBh = xh + e0 * 2;
    const char* pBl = xl + e0 * 2;

    float c[2][4][4];
#pragma unroll
    for (int i = 0; i < 2; i++)
#pragma unroll
        for (int j = 0; j < 4; j++)
#pragma unroll
            for (int q = 0; q < 4; q++) c[i][j][q] = 0.f;

    const int NIT = MCHUNK / 64;   // 32
    gram_load(sb + 0 * G_STAGE, pAh, pAl, pBh, pBl, 0, tid);
    CP_COMMIT();
    gram_load(sb + 1 * G_STAGE, pAh, pAl, pBh, pBl, 64, tid);
    CP_COMMIT();

    int s = 0;
    for (int it = 0; it < NIT; ++it) {
        if (it < NIT - 1) { CP_WAIT(1); } else { CP_WAIT(0); }
        __syncthreads();
        if (it + 2 < NIT) {
            int s2 = (s + 2 >= 3) ? (s - 1) : (s + 2);
            gram_load(sb + s2 * G_STAGE, pAh, pAl, pBh, pBl, (it + 2) * 64, tid);
            CP_COMMIT();
        }
        const uint32_t st = sb + s * G_STAGE;

#pragma unroll
        for (int ks = 0; ks < 4; ks++) {
            uint32_t aH[2][4], aL[2][4], bH[4][2], bL[4][2];
            const int mrowA = ks * 16 + ((l & 16) >> 1) + (l & 7);
            const uint32_t abase = st + mrowA * G_LDA + (wm * 32 + (l & 8)) * 2;
#pragma unroll
            for (int ma = 0; ma < 2; ma++) {
                uint32_t ad = abase + ma * 32;
                ldsm4t(aH[ma], ad);
                ldsm4t(aL[ma], ad + G_TILE);
            }
            const int mrowB = ks * 16 + (l & 15);
            const uint32_t bbase = st + 2 * G_TILE + mrowB * G_LDA + (wn * 32) * 2;
#pragma unroll
            for (int na = 0; na < 4; na++) {
                uint32_t bd = bbase + na * 16;
                ldsm2t(bH[na], bd);
                ldsm2t(bL[na], bd + G_TILE);
            }
#pragma unroll
            for (int ma = 0; ma < 2; ma++)
#pragma unroll
                for (int na = 0; na < 4; na++) {
                    mma_f16(c[ma][na], aH[ma], bH[na]);
                    mma_f16(c[ma][na], aH[ma], bL[na]);
                    mma_f16(c[ma][na], aL[ma], bH[na]);
                }
        }
        __syncthreads();
        s = (s + 1 >= 3) ? 0 : (s + 1);
    }

    float* G = g_energy + (size_t)b * DDIM * DDIM;
    const bool offdiag = (ti != tj);
#pragma unroll
    for (int ma = 0; ma < 2; ma++) {
        const int row0 = d0 + wm * 32 + ma * 16 + (l >> 2);
#pragma unroll
        for (int na = 0; na < 4; na++) {
            const int col = e0 + wn * 32 + na * 8 + (l & 3) * 2;
            atomicAdd(&G[(size_t)row0 * DDIM + col],           c[ma][na][0]);
            atomicAdd(&G[(size_t)row0 * DDIM + col + 1],       c[ma][na][1]);
            atomicAdd(&G[(size_t)(row0 + 8) * DDIM + col],     c[ma][na][2]);
            atomicAdd(&G[(size_t)(row0 + 8) * DDIM + col + 1], c[ma][na][3]);
            if (offdiag) {
                atomicAdd(&G[(size_t)col * DDIM + row0],           c[ma][na][0]);
                atomicAdd(&G[(size_t)(col + 1) * DDIM + row0],     c[ma][na][1]);
                atomicAdd(&G[(size_t)col * DDIM + row0 + 8],       c[ma][na][2]);
                atomicAdd(&G[(size_t)(col + 1) * DDIM + row0 + 8], c[ma][na][3]);
            }
        }
    }
}

// ---------------------------------------------------------------------------
// Kernel 2: softmax(-G) per row -> att fp16 ([d][e] layout)
// ---------------------------------------------------------------------------
__global__ void softmax_kernel() {
    const int b = blockIdx.y;
    const int d = blockIdx.x;
    const float* Grow = g_energy + (size_t)b * DDIM * DDIM + (size_t)d * DDIM;
    __half* A = g_att + (size_t)b * DDIM * DDIM + (size_t)d * DDIM;

    __shared__ float red[256];
    const int t = threadIdx.x;
    float v0 = Grow[t], v1 = Grow[t + 256];

    red[t] = fminf(v0, v1);
    __syncthreads();
#pragma unroll
    for (int s = 128; s > 0; s >>= 1) {
        if (t < s) red[t] = fminf(red[t], red[t + s]);
        __syncthreads();
    }
    const float gmin = red[0];
    __syncthreads();

    float p0 = expf(gmin - v0);
    float p1 = expf(gmin - v1);
    red[t] = p0 + p1;
    __syncthreads();
#pragma unroll
    for (int s = 128; s > 0; s >>= 1) {
        if (t < s) red[t] += red[t + s];
        __syncthreads();
    }
    const float inv = 1.f / red[0];
    A[t]       = __float2half_rn(p0 * inv);
    A[t + 256] = __float2half_rn(p1 * inv);
}

// ---------------------------------------------------------------------------
// Kernel 3: Y = gamma * (X @ Att^T) + X via mma.sync, 2 terms (Xh+Xl)*A.
// out[m, d] = sum_e X[m,e] * Att[d,e].  CTA 128(m)x128(d), BK=64, 3 stages.
// Smem tiles: [128 rows][64 k + 8 pad] fp16, row stride 144B. 3 tiles/stage.
// ---------------------------------------------------------------------------
#define Q_LDA   144
#define Q_TILE  (128 * Q_LDA)     // 18432
#define Q_STAGE (3 * Q_TILE)      // 55296
#define Q_SMEM  (3 * Q_STAGE)     // 165888

__device__ __forceinline__ void g2_load(uint32_t dst, const char* Ah, const char* Al,
                                        const char* Bt, int k0, int tid) {
    const char* srcs[3] = {Ah, Al, Bt};
#pragma unroll
    for (int t = 0; t < 3; t++) {
        uint32_t db = dst + t * Q_TILE;
        const char* sp = srcs[t] + k0 * 2;
#pragma unroll
        for (int j = 0; j < 2; j++) {
            int idx = tid + j * 512;
            int row = idx >> 3, c16 = idx & 7;
            cp16(db + row * Q_LDA + c16 * 16, sp + (size_t)row * 1024 + c16 * 16);
        }
    }
}

__global__ __launch_bounds__(512, 1) void gemm2_mma_kernel(const float* __restrict__ x,
                                                           const float* __restrict__ gam,
                                                           float* __restrict__ out) {
    const uint32_t sb = smem_u32(dyn_smem);
    const int tid = threadIdx.x, l = tid & 31, w = tid >> 5;
    const int wm = w & 3, wn = w >> 2;            // warp tile: 32 (m) x 32 (d)
    const int b = blockIdx.z, d0 = blockIdx.x * 128, m0 = blockIdx.y * 128;

    const char* Ah = (const char*)(g_x_hi + (size_t)b * MDIM * DDIM + (size_t)m0 * DDIM);
    const char* Al = (const char*)(g_x_lo + (size_t)b * MDIM * DDIM + (size_t)m0 * DDIM);
    const char* Bt = (const char*)(g_att + (size_t)b * DDIM * DDIM + (size_t)d0 * DDIM);

    float c[2][4][4];
#pragma unroll
    for (int i = 0; i < 2; i++)
#pragma unroll
        for (int j = 0; j < 4; j++)
#pragma unroll
            for (int q = 0; q < 4; q++) c[i][j][q] = 0.f;

    const int NIT = DDIM / 64;    // 8
    g2_load(sb + 0 * Q_STAGE, Ah, Al, Bt, 0, tid);
    CP_COMMIT();
    g2_load(sb + 1 * Q_STAGE, Ah, Al, Bt, 64, tid);
    CP_COMMIT();

    int s = 0;
    for (int it = 0; it < NIT; ++it) {
        if (it < NIT - 1) { CP_WAIT(1); } else { CP_WAIT(0); }
        __syncthreads();
        if (it + 2 < NIT) {
            int s2 = (s + 2 >= 3) ? (s - 1) : (s + 2);
            g2_load(sb + s2 * Q_STAGE, Ah, Al, Bt, (it + 2) * 64, tid);
            CP_COMMIT();
        }
        const uint32_t st = sb + s * Q_STAGE;

#pragma unroll
        for (int ks = 0; ks < 4; ks++) {
            uint32_t aH[2][4], aL[2][4], bb[4][2];
            const uint32_t akb = (ks * 16 + (l >> 4) * 8) * 2;
#pragma unroll
            for (int ma = 0; ma < 2; ma++) {
                const int arow = wm * 32 + ma * 16 + (l & 15);
                uint32_t ad = st + arow * Q_LDA + akb;
                ldsm4(aH[ma], ad);
                ldsm4(aL[ma], ad + Q_TILE);
            }
            const uint32_t bkb = (ks * 16 + ((l >> 3) & 1) * 8) * 2;
#pragma unroll
            for (int na = 0; na < 4; na++) {
                const int brow = wn * 32 + na * 8 + (l & 7);
                uint32_t bd = st + 2 * Q_TILE + brow * Q_LDA + bkb;
                ldsm2(bb[na], bd);
            }
#pragma unroll
            for (int ma = 0; ma < 2; ma++)
#pragma unroll
                for (int na = 0; na < 4; na++) {
                    mma_f16(c[ma][na], aH[ma], bb[na]);
                    mma_f16(c[ma][na], aL[ma], bb[na]);
                }
        }
        __syncthreads();
        s = (s + 1 >= 3) ? 0 : (s + 1);
    }

    const float gv = gam[0];
    const float* X = x + (size_t)b * MDIM * DDIM;
    float* Y = out + (size_t)b * MDIM * DDIM;
#pragma unroll
    for (int ma = 0; ma < 2; ma++) {
        const int row0 = m0 + wm * 32 + ma * 16 + (l >> 2);
#pragma unroll
        for (int na = 0; na < 4; na++) {
            const int col = d0 + wn * 32 + na * 8 + (l & 3) * 2;
            {
                float2 xv = *reinterpret_cast<const float2*>(X + (size_t)row0 * DDIM + col);
                *reinterpret_cast<float2*>(Y + (size_t)row0 * DDIM + col) =
                    make_float2(gv * c[ma][na][0] + xv.x, gv * c[ma][na][1] + xv.y);
            }
            {
                float2 xv = *reinterpret_cast<const float2*>(X + (size_t)(row0 + 8) * DDIM + col);
                *reinterpret_cast<float2*>(Y + (size_t)(row0 + 8) * DDIM + col) =
                    make_float2(gv * c[ma][na][2] + xv.x, gv * c[ma][na][3] + xv.y);
            }
        }
    }
}

// ---------------------------------------------------------------------------
extern "C" void kernel_launch(void* const* d_in, const int* in_sizes, int n_in,
                              void* d_out, int out_size) {
    const float* x     = (const float*)d_in[0];
    const float* gamma = (const float*)d_in[1];
    float* out = (float*)d_out;

    cudaFuncSetAttribute(gram_mma_kernel, cudaFuncAttributeMaxDynamicSharedMemorySize, G_SMEM);
    cudaFuncSetAttribute(gemm2_mma_kernel, cudaFuncAttributeMaxDynamicSharedMemorySize, Q_SMEM);

    zero_energy_kernel<<<1024, 256>>>();
    split_kernel<<<4096, 256>>>(x);
    gram_mma_kernel<<<dim3(10, KSPLIT, BATCH), 512, G_SMEM>>>();
    softmax_kernel<<<dim3(DDIM, BATCH), 256>>>();
    gemm2_mma_kernel<<<dim3(4, MDIM / 128, BATCH), 512, Q_SMEM>>>(x, gamma, out);
}

// round 10
// speedup vs baseline: 4.5622x; 1.2345x over previous
#include <cuda_runtime.h>
#include <cuda_fp16.h>
#include <cstdint>
#include <math.h>

#define BATCH 8
#define MDIM  16384
#define DDIM  512

// ---------------- scratch (device globals; no allocations allowed) ----------
__device__ __half g_x_hi[(size_t)BATCH * MDIM * DDIM];    // X hi (128MB)
__device__ __half g_x_lo[(size_t)BATCH * MDIM * DDIM];    // X lo (128MB)
__device__ float  g_energy[(size_t)BATCH * DDIM * DDIM];  // G    (8MB)
__device__ __half g_att[(size_t)BATCH * DDIM * DDIM];     // A    (4MB)

// ---------------- helpers ----------------
__device__ __forceinline__ uint32_t smem_u32(const void* p) {
    uint32_t a;
    asm("{ .reg .u64 t; cvta.to.shared.u64 t, %1; cvt.u32.u64 %0, t; }" : "=r"(a) : "l"(p));
    return a;
}
__device__ __forceinline__ void cp16(uint32_t dst, const void* src) {
    asm volatile("cp.async.cg.shared.global [%0], [%1], 16;" :: "r"(dst), "l"(src));
}
#define CP_COMMIT() asm volatile("cp.async.commit_group;" ::: "memory")
#define CP_WAIT(n)  asm volatile("cp.async.wait_group %0;" :: "n"(n) : "memory")

__device__ __forceinline__ void mma_f16(float* c, const uint32_t* a, const uint32_t* b) {
    asm volatile(
        "mma.sync.aligned.m16n8k16.row.col.f32.f16.f16.f32 "
        "{%0,%1,%2,%3}, {%4,%5,%6,%7}, {%8,%9}, {%0,%1,%2,%3};"
        : "+f"(c[0]), "+f"(c[1]), "+f"(c[2]), "+f"(c[3])
        : "r"(a[0]), "r"(a[1]), "r"(a[2]), "r"(a[3]), "r"(b[0]), "r"(b[1]));
}
__device__ __forceinline__ void ldsm4(uint32_t* r, uint32_t a) {
    asm volatile("ldmatrix.sync.aligned.m8n8.x4.shared.b16 {%0,%1,%2,%3}, [%4];"
                 : "=r"(r[0]), "=r"(r[1]), "=r"(r[2]), "=r"(r[3]) : "r"(a));
}
__device__ __forceinline__ void ldsm4t(uint32_t* r, uint32_t a) {
    asm volatile("ldmatrix.sync.aligned.m8n8.x4.trans.shared.b16 {%0,%1,%2,%3}, [%4];"
                 : "=r"(r[0]), "=r"(r[1]), "=r"(r[2]), "=r"(r[3]) : "r"(a));
}

// ---------------------------------------------------------------------------
// Kernel Z: zero g_energy (atomic accumulation target)
// ---------------------------------------------------------------------------
__global__ void zero_energy_kernel() {
    const size_t n4 = (size_t)BATCH * DDIM * DDIM / 4;
    const size_t stride = (size_t)gridDim.x * blockDim.x;
    for (size_t i = (size_t)blockIdx.x * blockDim.x + threadIdx.x; i < n4; i += stride)
        reinterpret_cast<float4*>(g_energy)[i] = make_float4(0.f, 0.f, 0.f, 0.f);
}

// ---------------------------------------------------------------------------
// Kernel 0: fp16 hi/lo split of x (natural [m, d] layout)
// ---------------------------------------------------------------------------
__global__ void split_kernel(const float* __restrict__ x) {
    const size_t n4 = (size_t)BATCH * MDIM * DDIM / 4;
    const size_t stride = (size_t)gridDim.x * blockDim.x;
    for (size_t i = (size_t)blockIdx.x * blockDim.x + threadIdx.x; i < n4; i += stride) {
        float4 v = reinterpret_cast<const float4*>(x)[i];
        __half h0 = __float2half_rn(v.x), h1 = __float2half_rn(v.y);
        __half h2 = __float2half_rn(v.z), h3 = __float2half_rn(v.w);
        __half l0 = __float2half_rn(v.x - __half2float(h0));
        __half l1 = __float2half_rn(v.y - __half2float(h1));
        __half l2 = __float2half_rn(v.z - __half2float(h2));
        __half l3 = __float2half_rn(v.w - __half2float(h3));
        uint2 hw, lw;
        hw.x = ((uint32_t)__half_as_ushort(h1) << 16) | __half_as_ushort(h0);
        hw.y = ((uint32_t)__half_as_ushort(h3) << 16) | __half_as_ushort(h2);
        lw.x = ((uint32_t)__half_as_ushort(l1) << 16) | __half_as_ushort(l0);
        lw.y = ((uint32_t)__half_as_ushort(l3) << 16) | __half_as_ushort(l2);
        reinterpret_cast<uint2*>(g_x_hi)[i] = hw;
        reinterpret_cast<uint2*>(g_x_lo)[i] = lw;
    }
}

// ---------------------------------------------------------------------------
// Kernel 1: Gram via mma.sync, symmetric pairs + K-split-16, 3-stage pipeline.
// G[d,e] = sum_m X[m,d]*X[m,e].  512 threads, warp tile 32x32.
// Smem panel: [64 m-rows][128 cols + 8 pad] fp16, row stride 272B.
// ---------------------------------------------------------------------------
#define G_LDA   272
#define G_TILE  (64 * G_LDA)      // 17408
#define G_STAGE (4 * G_TILE)      // 69632
#define G_SMEM  (3 * G_STAGE)     // 208896
#define KSPLIT  16
#define MCHUNK  (MDIM / KSPLIT)   // 1024

__constant__ int c_pair_ti[10] = {0,0,0,0,1,1,1,2,2,3};
__constant__ int c_pair_tj[10] = {0,1,2,3,1,2,3,2,3,3};

__device__ __forceinline__ void gram_load(uint32_t dst, const char* Ah, const char* Al,
                                          const char* Bh, const char* Bl, int m0, int tid) {
    const char* srcs[4] = {Ah, Al, Bh, Bl};
#pragma unroll
    for (int t = 0; t < 4; t++) {
        uint32_t db = dst + t * G_TILE;
        const char* sp = srcs[t] + (size_t)m0 * 1024;
#pragma unroll
        for (int j = 0; j < 2; j++) {
            int idx = tid + j * 512;
            int row = idx >> 4, c16 = idx & 15;
            cp16(db + row * G_LDA + c16 * 16, sp + (size_t)row * 1024 + c16 * 16);
        }
    }
}

extern __shared__ char dyn_smem[];

__global__ __launch_bounds__(512, 1) void gram_mma_kernel() {
    const uint32_t sb = smem_u32(dyn_smem);
    const int tid = threadIdx.x, l = tid & 31, w = tid >> 5;
    const int wm = w & 3, wn = w >> 2;            // warp tile: 32 (d) x 32 (e)
    const int b = blockIdx.z;
    const int ti = c_pair_ti[blockIdx.x], tj = c_pair_tj[blockIdx.x];
    const int d0 = ti * 128, e0 = tj * 128;
    const int mbase = blockIdx.y * MCHUNK;

    const char* xh = (const char*)(g_x_hi + (size_t)b * MDIM * DDIM) + (size_t)mbase * 1024;
    const char* xl = (const char*)(g_x_lo + (size_t)b * MDIM * DDIM) + (size_t)mbase * 1024;
    const char* pAh = xh + d0 * 2;
    const char* pAl = xl + d0 * 2;
    const char* pBh = xh + e0 * 2;
    const char* pBl = xl + e0 * 2;

    float c[2][4][4];
#pragma unroll
    for (int i = 0; i < 2; i++)
#pragma unroll
        for (int j = 0; j < 4; j++)
#pragma unroll
            for (int q = 0; q < 4; q++) c[i][j][q] = 0.f;

    const int NIT = MCHUNK / 64;   // 16
    gram_load(sb + 0 * G_STAGE, pAh, pAl, pBh, pBl, 0, tid);
    CP_COMMIT();
    gram_load(sb + 1 * G_STAGE, pAh, pAl, pBh, pBl, 64, tid);
    CP_COMMIT();

    int s = 0;
    for (int it = 0; it < NIT; ++it) {
        if (it < NIT - 1) { CP_WAIT(1); } else { CP_WAIT(0); }
        __syncthreads();
        if (it + 2 < NIT) {
            int s2 = (s + 2 >= 3) ? (s - 1) : (s + 2);
            gram_load(sb + s2 * G_STAGE, pAh, pAl, pBh, pBl, (it + 2) * 64, tid);
            CP_COMMIT();
        }
        const uint32_t st = sb + s * G_STAGE;

#pragma unroll
        for (int ks = 0; ks < 4; ks++) {
            uint32_t aH[2][4], aL[2][4], bH[4][2], bL[4][2];
            // 16x16 trans-ldmatrix lane footprint: rows (l&7)+8*(l>=16), col +16B if (l&8)
            const int mrow = ks * 16 + ((l & 16) >> 1) + (l & 7);
            const uint32_t abase = st + mrow * G_LDA + (wm * 32 + (l & 8)) * 2;
#pragma unroll
            for (int ma = 0; ma < 2; ma++) {
                uint32_t ad = abase + ma * 32;
                ldsm4t(aH[ma], ad);
                ldsm4t(aL[ma], ad + G_TILE);
            }
            // B: load n-tile PAIRS via ldsm4t (16 k-rows x 16 e-cols)
            const uint32_t bbase = st + 2 * G_TILE + mrow * G_LDA + (wn * 32 + (l & 8)) * 2;
#pragma unroll
            for (int p = 0; p < 2; p++) {
                uint32_t r[4];
                uint32_t bd = bbase + p * 32;
                ldsm4t(r, bd);
                bH[2 * p][0] = r[0]; bH[2 * p][1] = r[2];
                bH[2 * p + 1][0] = r[1]; bH[2 * p + 1][1] = r[3];
                ldsm4t(r, bd + G_TILE);
                bL[2 * p][0] = r[0]; bL[2 * p][1] = r[2];
                bL[2 * p + 1][0] = r[1]; bL[2 * p + 1][1] = r[3];
            }
#pragma unroll
            for (int ma = 0; ma < 2; ma++)
#pragma unroll
                for (int na = 0; na < 4; na++) {
                    mma_f16(c[ma][na], aH[ma], bH[na]);
                    mma_f16(c[ma][na], aH[ma], bL[na]);
                    mma_f16(c[ma][na], aL[ma], bH[na]);
                }
        }
        __syncthreads();
        s = (s + 1 >= 3) ? 0 : (s + 1);
    }

    float* G = g_energy + (size_t)b * DDIM * DDIM;
    const bool offdiag = (ti != tj);
#pragma unroll
    for (int ma = 0; ma < 2; ma++) {
        const int row0 = d0 + wm * 32 + ma * 16 + (l >> 2);
#pragma unroll
        for (int na = 0; na < 4; na++) {
            const int col = e0 + wn * 32 + na * 8 + (l & 3) * 2;
            atomicAdd(&G[(size_t)row0 * DDIM + col],           c[ma][na][0]);
            atomicAdd(&G[(size_t)row0 * DDIM + col + 1],       c[ma][na][1]);
            atomicAdd(&G[(size_t)(row0 + 8) * DDIM + col],     c[ma][na][2]);
            atomicAdd(&G[(size_t)(row0 + 8) * DDIM + col + 1], c[ma][na][3]);
            if (offdiag) {
                atomicAdd(&G[(size_t)col * DDIM + row0],           c[ma][na][0]);
                atomicAdd(&G[(size_t)(col + 1) * DDIM + row0],     c[ma][na][1]);
                atomicAdd(&G[(size_t)col * DDIM + row0 + 8],       c[ma][na][2]);
                atomicAdd(&G[(size_t)(col + 1) * DDIM + row0 + 8], c[ma][na][3]);
            }
        }
    }
}

// ---------------------------------------------------------------------------
// Kernel 2: softmax(-G) per row -> att fp16 ([d][e] layout)
// ---------------------------------------------------------------------------
__global__ void softmax_kernel() {
    const int b = blockIdx.y;
    const int d = blockIdx.x;
    const float* Grow = g_energy + (size_t)b * DDIM * DDIM + (size_t)d * DDIM;
    __half* A = g_att + (size_t)b * DDIM * DDIM + (size_t)d * DDIM;

    __shared__ float red[256];
    const int t = threadIdx.x;
    float v0 = Grow[t], v1 = Grow[t + 256];

    red[t] = fminf(v0, v1);
    __syncthreads();
#pragma unroll
    for (int s = 128; s > 0; s >>= 1) {
        if (t < s) red[t] = fminf(red[t], red[t + s]);
        __syncthreads();
    }
    const float gmin = red[0];
    __syncthreads();

    float p0 = expf(gmin - v0);
    float p1 = expf(gmin - v1);
    red[t] = p0 + p1;
    __syncthreads();
#pragma unroll
    for (int s = 128; s > 0; s >>= 1) {
        if (t < s) red[t] += red[t + s];
        __syncthreads();
    }
    const float inv = 1.f / red[0];
    A[t]       = __float2half_rn(p0 * inv);
    A[t + 256] = __float2half_rn(p1 * inv);
}

// ---------------------------------------------------------------------------
// Kernel 3: Y = gamma * (Xh @ Att^T) + X via mma.sync, 1 term.
// out[m, d] = sum_e X[m,e] * Att[d,e].  CTA 128(m)x128(d), BK=64, 3 stages.
// Smem tiles: [128 rows][64 k + 8 pad] fp16, row stride 144B. 2 tiles/stage.
// ---------------------------------------------------------------------------
#define Q_LDA   144
#define Q_TILE  (128 * Q_LDA)     // 18432
#define Q_STAGE (2 * Q_TILE)      // 36864
#define Q_SMEM  (3 * Q_STAGE)     // 110592

__device__ __forceinline__ void g2_load(uint32_t dst, const char* Ah,
                                        const char* Bt, int k0, int tid) {
    const char* srcs[2] = {Ah, Bt};
#pragma unroll
    for (int t = 0; t < 2; t++) {
        uint32_t db = dst + t * Q_TILE;
        const char* sp = srcs[t] + k0 * 2;
#pragma unroll
        for (int j = 0; j < 2; j++) {
            int idx = tid + j * 512;
            int row = idx >> 3, c16 = idx & 7;
            cp16(db + row * Q_LDA + c16 * 16, sp + (size_t)row * 1024 + c16 * 16);
        }
    }
}

__global__ __launch_bounds__(512, 1) void gemm2_mma_kernel(const float* __restrict__ x,
                                                           const float* __restrict__ gam,
                                                           float* __restrict__ out) {
    const uint32_t sb = smem_u32(dyn_smem);
    const int tid = threadIdx.x, l = tid & 31, w = tid >> 5;
    const int wm = w & 3, wn = w >> 2;            // warp tile: 32 (m) x 32 (d)
    const int b = blockIdx.z, d0 = blockIdx.x * 128, m0 = blockIdx.y * 128;

    const char* Ah = (const char*)(g_x_hi + (size_t)b * MDIM * DDIM + (size_t)m0 * DDIM);
    const char* Bt = (const char*)(g_att + (size_t)b * DDIM * DDIM + (size_t)d0 * DDIM);

    float c[2][4][4];
#pragma unroll
    for (int i = 0; i < 2; i++)
#pragma unroll
        for (int j = 0; j < 4; j++)
#pragma unroll
            for (int q = 0; q < 4; q++) c[i][j][q] = 0.f;

    const int NIT = DDIM / 64;    // 8
    g2_load(sb + 0 * Q_STAGE, Ah, Bt, 0, tid);
    CP_COMMIT();
    g2_load(sb + 1 * Q_STAGE, Ah, Bt, 64, tid);
    CP_COMMIT();

    int s = 0;
    for (int it = 0; it < NIT; ++it) {
        if (it < NIT - 1) { CP_WAIT(1); } else { CP_WAIT(0); }
        __syncthreads();
        if (it + 2 < NIT) {
            int s2 = (s + 2 >= 3) ? (s - 1) : (s + 2);
            g2_load(sb + s2 * Q_STAGE, Ah, Bt, (it + 2) * 64, tid);
            CP_COMMIT();
        }
        const uint32_t st = sb + s * Q_STAGE;

#pragma unroll
        for (int ks = 0; ks < 4; ks++) {
            uint32_t aH[2][4], bb[4][2];
            const uint32_t akb = (ks * 16 + (l >> 4) * 8) * 2;
#pragma unroll
            for (int ma = 0; ma < 2; ma++) {
                const int arow = wm * 32 + ma * 16 + (l & 15);
                uint32_t ad = st + arow * Q_LDA + akb;
                ldsm4(aH[ma], ad);
            }
            // B: load n-tile PAIRS via ldsm4 (16 n-rows x 16 k-cols)
            {
                const int mloc = l >> 3;   // matrix index 0..3
#pragma unroll
                for (int p = 0; p < 2; p++) {
                    const int brow = wn * 32 + p * 16 + ((mloc >> 1) << 3) + (l & 7);
                    const uint32_t bkb = (ks * 16 + (mloc & 1) * 8) * 2;
                    uint32_t r[4];
                    ldsm4(r, st + Q_TILE + brow * Q_LDA + bkb);
                    bb[2 * p][0] = r[0]; bb[2 * p][1] = r[1];
                    bb[2 * p + 1][0] = r[2]; bb[2 * p + 1][1] = r[3];
                }
            }
#pragma unroll
            for (int ma = 0; ma < 2; ma++)
#pragma unroll
                for (int na = 0; na < 4; na++)
                    mma_f16(c[ma][na], aH[ma], bb[na]);
        }
        __syncthreads();
        s = (s + 1 >= 3) ? 0 : (s + 1);
    }

    const float gv = gam[0];
    const float* X = x + (size_t)b * MDIM * DDIM;
    float* Y = out + (size_t)b * MDIM * DDIM;
#pragma unroll
    for (int ma = 0; ma < 2; ma++) {
        const int row0 = m0 + wm * 32 + ma * 16 + (l >> 2);
#pragma unroll
        for (int na = 0; na < 4; na++) {
            const int col = d0 + wn * 32 + na * 8 + (l & 3) * 2;
            {
                float2 xv = *reinterpret_cast<const float2*>(X + (size_t)row0 * DDIM + col);
                *reinterpret_cast<float2*>(Y + (size_t)row0 * DDIM + col) =
                    make_float2(gv * c[ma][na][0] + xv.x, gv * c[ma][na][1] + xv.y);
            }
            {
                float2 xv = *reinterpret_cast<const float2*>(X + (size_t)(row0 + 8) * DDIM + col);
                *reinterpret_cast<float2*>(Y + (size_t)(row0 + 8) * DDIM + col) =
                    make_float2(gv * c[ma][na][2] + xv.x, gv * c[ma][na][3] + xv.y);
            }
        }
    }
}

// ---------------------------------------------------------------------------
extern "C" void kernel_launch(void* const* d_in, const int* in_sizes, int n_in,
                              void* d_out, int out_size) {
    const float* x     = (const float*)d_in[0];
    const float* gamma = (const float*)d_in[1];
    float* out = (float*)d_out;

    cudaFuncSetAttribute(gram_mma_kernel, cudaFuncAttributeMaxDynamicSharedMemorySize, G_SMEM);
    cudaFuncSetAttribute(gemm2_mma_kernel, cudaFuncAttributeMaxDynamicSharedMemorySize, Q_SMEM);

    zero_energy_kernel<<<1024, 256>>>();
    split_kernel<<<4096, 256>>>(x);
    gram_mma_kernel<<<dim3(10, KSPLIT, BATCH), 512, G_SMEM>>>();
    softmax_kernel<<<dim3(DDIM, BATCH), 256>>>();
    gemm2_mma_kernel<<<dim3(4, MDIM / 128, BATCH), 512, Q_SMEM>>>(x, gamma, out);
}

// round 11
// speedup vs baseline: 4.7297x; 1.0367x over previous
#include <cuda_runtime.h>
#include <cuda_fp16.h>
#include <cstdint>
#include <math.h>

#define BATCH 8
#define MDIM  16384
#define DDIM  512

// ---------------- scratch (device globals; no allocations allowed) ----------
__device__ __half g_x_hi[(size_t)BATCH * MDIM * DDIM];    // X hi (128MB)
__device__ __half g_x_lo[(size_t)BATCH * MDIM * DDIM];    // X lo (128MB)
__device__ float  g_energy[(size_t)BATCH * DDIM * DDIM];  // G    (8MB)
__device__ __half g_att[(size_t)BATCH * DDIM * DDIM];     // A    (4MB)

// ---------------- helpers ----------------
__device__ __forceinline__ uint32_t smem_u32(const void* p) {
    uint32_t a;
    asm("{ .reg .u64 t; cvta.to.shared.u64 t, %1; cvt.u32.u64 %0, t; }" : "=r"(a) : "l"(p));
    return a;
}
__device__ __forceinline__ void cp16(uint32_t dst, const void* src) {
    asm volatile("cp.async.cg.shared.global [%0], [%1], 16;" :: "r"(dst), "l"(src));
}
#define CP_COMMIT() asm volatile("cp.async.commit_group;" ::: "memory")
#define CP_WAIT(n)  asm volatile("cp.async.wait_group %0;" :: "n"(n) : "memory")

__device__ __forceinline__ void mma_f16(float* c, const uint32_t* a, const uint32_t* b) {
    asm volatile(
        "mma.sync.aligned.m16n8k16.row.col.f32.f16.f16.f32 "
        "{%0,%1,%2,%3}, {%4,%5,%6,%7}, {%8,%9}, {%0,%1,%2,%3};"
        : "+f"(c[0]), "+f"(c[1]), "+f"(c[2]), "+f"(c[3])
        : "r"(a[0]), "r"(a[1]), "r"(a[2]), "r"(a[3]), "r"(b[0]), "r"(b[1]));
}
__device__ __forceinline__ void ldsm4(uint32_t* r, uint32_t a) {
    asm volatile("ldmatrix.sync.aligned.m8n8.x4.shared.b16 {%0,%1,%2,%3}, [%4];"
                 : "=r"(r[0]), "=r"(r[1]), "=r"(r[2]), "=r"(r[3]) : "r"(a));
}
__device__ __forceinline__ void ldsm4t(uint32_t* r, uint32_t a) {
    asm volatile("ldmatrix.sync.aligned.m8n8.x4.trans.shared.b16 {%0,%1,%2,%3}, [%4];"
                 : "=r"(r[0]), "=r"(r[1]), "=r"(r[2]), "=r"(r[3]) : "r"(a));
}

// ---------------------------------------------------------------------------
// Kernel 0: fp16 hi/lo split of x + zero g_energy (fused)
// ---------------------------------------------------------------------------
__global__ void split_kernel(const float* __restrict__ x) {
    const size_t stride = (size_t)gridDim.x * blockDim.x;
    // zero the atomic accumulation target
    const size_t ne4 = (size_t)BATCH * DDIM * DDIM / 4;
    for (size_t i = (size_t)blockIdx.x * blockDim.x + threadIdx.x; i < ne4; i += stride)
        reinterpret_cast<float4*>(g_energy)[i] = make_float4(0.f, 0.f, 0.f, 0.f);
    // split
    const size_t n4 = (size_t)BATCH * MDIM * DDIM / 4;
    for (size_t i = (size_t)blockIdx.x * blockDim.x + threadIdx.x; i < n4; i += stride) {
        float4 v = reinterpret_cast<const float4*>(x)[i];
        __half h0 = __float2half_rn(v.x), h1 = __float2half_rn(v.y);
        __half h2 = __float2half_rn(v.z), h3 = __float2half_rn(v.w);
        __half l0 = __float2half_rn(v.x - __half2float(h0));
        __half l1 = __float2half_rn(v.y - __half2float(h1));
        __half l2 = __float2half_rn(v.z - __half2float(h2));
        __half l3 = __float2half_rn(v.w - __half2float(h3));
        uint2 hw, lw;
        hw.x = ((uint32_t)__half_as_ushort(h1) << 16) | __half_as_ushort(h0);
        hw.y = ((uint32_t)__half_as_ushort(h3) << 16) | __half_as_ushort(h2);
        lw.x = ((uint32_t)__half_as_ushort(l1) << 16) | __half_as_ushort(l0);
        lw.y = ((uint32_t)__half_as_ushort(l3) << 16) | __half_as_ushort(l2);
        reinterpret_cast<uint2*>(g_x_hi)[i] = hw;
        reinterpret_cast<uint2*>(g_x_lo)[i] = lw;
    }
}

// ---------------------------------------------------------------------------
// Kernel 1: Gram via mma.sync, symmetric pairs + K-split-16, 3-stage pipeline.
// Top-sync-only mainloop (write stage s+2 never aliases read stage s).
// ---------------------------------------------------------------------------
#define G_LDA   272
#define G_TILE  (64 * G_LDA)      // 17408
#define G_STAGE (4 * G_TILE)      // 69632
#define G_SMEM  (3 * G_STAGE)     // 208896
#define KSPLIT  16
#define MCHUNK  (MDIM / KSPLIT)   // 1024

__constant__ int c_pair_ti[10] = {0,0,0,0,1,1,1,2,2,3};
__constant__ int c_pair_tj[10] = {0,1,2,3,1,2,3,2,3,3};

__device__ __forceinline__ void gram_load(uint32_t dst, const char* Ah, const char* Al,
                                          const char* Bh, const char* Bl, int m0, int tid) {
    const char* srcs[4] = {Ah, Al, Bh, Bl};
#pragma unroll
    for (int t = 0; t < 4; t++) {
        uint32_t db = dst + t * G_TILE;
        const char* sp = srcs[t] + (size_t)m0 * 1024;
#pragma unroll
        for (int j = 0; j < 2; j++) {
            int idx = tid + j * 512;
            int row = idx >> 4, c16 = idx & 15;
            cp16(db + row * G_LDA + c16 * 16, sp + (size_t)row * 1024 + c16 * 16);
        }
    }
}

extern __shared__ char dyn_smem[];

__global__ __launch_bounds__(512, 1) void gram_mma_kernel() {
    const uint32_t sb = smem_u32(dyn_smem);
    const int tid = threadIdx.x, l = tid & 31, w = tid >> 5;
    const int wm = w & 3, wn = w >> 2;            // warp tile: 32 (d) x 32 (e)
    const int b = blockIdx.z;
    const int ti = c_pair_ti[blockIdx.x], tj = c_pair_tj[blockIdx.x];
    const int d0 = ti * 128, e0 = tj * 128;
    const int mbase = blockIdx.y * MCHUNK;

    const char* xh = (const char*)(g_x_hi + (size_t)b * MDIM * DDIM) + (size_t)mbase * 1024;
    const char* xl = (const char*)(g_x_lo + (size_t)b * MDIM * DDIM) + (size_t)mbase * 1024;
    const char* pAh = xh + d0 * 2;
    const char* pAl = xl + d0 * 2;
    const char* pBh = xh + e0 * 2;
    const char* pBl = xl + e0 * 2;

    float c[2][4][4];
#pragma unroll
    for (int i = 0; i < 2; i++)
#pragma unroll
        for (int j = 0; j < 4; j++)
#pragma unroll
            for (int q = 0; q < 4; q++) c[i][j][q] = 0.f;

    const int NIT = MCHUNK / 64;   // 16
    gram_load(sb + 0 * G_STAGE, pAh, pAl, pBh, pBl, 0, tid);
    CP_COMMIT();
    gram_load(sb + 1 * G_STAGE, pAh, pAl, pBh, pBl, 64, tid);
    CP_COMMIT();

    int s = 0;
    for (int it = 0; it < NIT; ++it) {
        if (it < NIT - 1) { CP_WAIT(1); } else { CP_WAIT(0); }
        __syncthreads();
        if (it + 2 < NIT) {
            int s2 = (s + 2 >= 3) ? (s - 1) : (s + 2);
            gram_load(sb + s2 * G_STAGE, pAh, pAl, pBh, pBl, (it + 2) * 64, tid);
            CP_COMMIT();
        }
        const uint32_t st = sb + s * G_STAGE;

#pragma unroll
        for (int ks = 0; ks < 4; ks++) {
            uint32_t aH[2][4], aL[2][4], bH[4][2], bL[4][2];
            const int mrow = ks * 16 + ((l & 16) >> 1) + (l & 7);
            const uint32_t abase = st + mrow * G_LDA + (wm * 32 + (l & 8)) * 2;
#pragma unroll
            for (int ma = 0; ma < 2; ma++) {
                uint32_t ad = abase + ma * 32;
                ldsm4t(aH[ma], ad);
                ldsm4t(aL[ma], ad + G_TILE);
            }
            const uint32_t bbase = st + 2 * G_TILE + mrow * G_LDA + (wn * 32 + (l & 8)) * 2;
#pragma unroll
            for (int p = 0; p < 2; p++) {
                uint32_t r[4];
                uint32_t bd = bbase + p * 32;
                ldsm4t(r, bd);
                bH[2 * p][0] = r[0]; bH[2 * p][1] = r[2];
                bH[2 * p + 1][0] = r[1]; bH[2 * p + 1][1] = r[3];
                ldsm4t(r, bd + G_TILE);
                bL[2 * p][0] = r[0]; bL[2 * p][1] = r[2];
                bL[2 * p + 1][0] = r[1]; bL[2 * p + 1][1] = r[3];
            }
#pragma unroll
            for (int ma = 0; ma < 2; ma++)
#pragma unroll
                for (int na = 0; na < 4; na++) {
                    mma_f16(c[ma][na], aH[ma], bH[na]);
                    mma_f16(c[ma][na], aH[ma], bL[na]);
                    mma_f16(c[ma][na], aL[ma], bH[na]);
                }
        }
        // no trailing sync: next iteration's top sync orders reuse of this stage
        s = (s + 1 >= 3) ? 0 : (s + 1);
    }

    float* G = g_energy + (size_t)b * DDIM * DDIM;
    const bool offdiag = (ti != tj);
#pragma unroll
    for (int ma = 0; ma < 2; ma++) {
        const int row0 = d0 + wm * 32 + ma * 16 + (l >> 2);
#pragma unroll
        for (int na = 0; na < 4; na++) {
            const int col = e0 + wn * 32 + na * 8 + (l & 3) * 2;
            atomicAdd(&G[(size_t)row0 * DDIM + col],           c[ma][na][0]);
            atomicAdd(&G[(size_t)row0 * DDIM + col + 1],       c[ma][na][1]);
            atomicAdd(&G[(size_t)(row0 + 8) * DDIM + col],     c[ma][na][2]);
            atomicAdd(&G[(size_t)(row0 + 8) * DDIM + col + 1], c[ma][na][3]);
            if (offdiag) {
                atomicAdd(&G[(size_t)col * DDIM + row0],           c[ma][na][0]);
                atomicAdd(&G[(size_t)(col + 1) * DDIM + row0],     c[ma][na][1]);
                atomicAdd(&G[(size_t)col * DDIM + row0 + 8],       c[ma][na][2]);
                atomicAdd(&G[(size_t)(col + 1) * DDIM + row0 + 8], c[ma][na][3]);
            }
        }
    }
}

// ---------------------------------------------------------------------------
// Kernel 2: softmax(-G) per row -> att fp16 ([d][e] layout)
// ---------------------------------------------------------------------------
__global__ void softmax_kernel() {
    const int b = blockIdx.y;
    const int d = blockIdx.x;
    const float* Grow = g_energy + (size_t)b * DDIM * DDIM + (size_t)d * DDIM;
    __half* A = g_att + (size_t)b * DDIM * DDIM + (size_t)d * DDIM;

    __shared__ float red[256];
    const int t = threadIdx.x;
    float v0 = Grow[t], v1 = Grow[t + 256];

    red[t] = fminf(v0, v1);
    __syncthreads();
#pragma unroll
    for (int s = 128; s > 0; s >>= 1) {
        if (t < s) red[t] = fminf(red[t], red[t + s]);
        __syncthreads();
    }
    const float gmin = red[0];
    __syncthreads();

    float p0 = expf(gmin - v0);
    float p1 = expf(gmin - v1);
    red[t] = p0 + p1;
    __syncthreads();
#pragma unroll
    for (int s = 128; s > 0; s >>= 1) {
        if (t < s) red[t] += red[t + s];
        __syncthreads();
    }
    const float inv = 1.f / red[0];
    A[t]       = __float2half_rn(p0 * inv);
    A[t + 256] = __float2half_rn(p1 * inv);
}

// ---------------------------------------------------------------------------
// Kernel 3: Y = gamma * (Xh @ Att^T) + X via mma.sync, 1 term, 4-stage pipe.
// Top-sync-only mainloop.
// ---------------------------------------------------------------------------
#define Q_LDA   144
#define Q_TILE  (128 * Q_LDA)     // 18432
#define Q_STAGE (2 * Q_TILE)      // 36864
#define Q_NSTG  4
#define Q_SMEM  (Q_NSTG * Q_STAGE)  // 147456

__device__ __forceinline__ void g2_load(uint32_t dst, const char* Ah,
                                        const char* Bt, int k0, int tid) {
    const char* srcs[2] = {Ah, Bt};
#pragma unroll
    for (int t = 0; t < 2; t++) {
        uint32_t db = dst + t * Q_TILE;
        const char* sp = srcs[t] + k0 * 2;
#pragma unroll
        for (int j = 0; j < 2; j++) {
            int idx = tid + j * 512;
            int row = idx >> 3, c16 = idx & 7;
            cp16(db + row * Q_LDA + c16 * 16, sp + (size_t)row * 1024 + c16 * 16);
        }
    }
}

__global__ __launch_bounds__(512, 1) void gemm2_mma_kernel(const float* __restrict__ x,
                                                           const float* __restrict__ gam,
                                                           float* __restrict__ out) {
    const uint32_t sb = smem_u32(dyn_smem);
    const int tid = threadIdx.x, l = tid & 31, w = tid >> 5;
    const int wm = w & 3, wn = w >> 2;            // warp tile: 32 (m) x 32 (d)
    const int b = blockIdx.z, d0 = blockIdx.x * 128, m0 = blockIdx.y * 128;

    const char* Ah = (const char*)(g_x_hi + (size_t)b * MDIM * DDIM + (size_t)m0 * DDIM);
    const char* Bt = (const char*)(g_att + (size_t)b * DDIM * DDIM + (size_t)d0 * DDIM);

    float c[2][4][4];
#pragma unroll
    for (int i = 0; i < 2; i++)
#pragma unroll
        for (int j = 0; j < 4; j++)
#pragma unroll
            for (int q = 0; q < 4; q++) c[i][j][q] = 0.f;

    const int NIT = DDIM / 64;    // 8
    g2_load(sb + 0 * Q_STAGE, Ah, Bt, 0, tid);
    CP_COMMIT();
    g2_load(sb + 1 * Q_STAGE, Ah, Bt, 64, tid);
    CP_COMMIT();
    g2_load(sb + 2 * Q_STAGE, Ah, Bt, 128, tid);
    CP_COMMIT();

    int s = 0;
    for (int it = 0; it < NIT; ++it) {
        if (it < NIT - 2)      { CP_WAIT(2); }
        else if (it == NIT - 2){ CP_WAIT(1); }
        else                   { CP_WAIT(0); }
        __syncthreads();
        if (it + 3 < NIT) {
            int s3 = s + 3; if (s3 >= Q_NSTG) s3 -= Q_NSTG;
            g2_load(sb + s3 * Q_STAGE, Ah, Bt, (it + 3) * 64, tid);
            CP_COMMIT();
        }
        const uint32_t st = sb + s * Q_STAGE;

#pragma unroll
        for (int ks = 0; ks < 4; ks++) {
            uint32_t aH[2][4], bb[4][2];
            const uint32_t akb = (ks * 16 + (l >> 4) * 8) * 2;
#pragma unroll
            for (int ma = 0; ma < 2; ma++) {
                const int arow = wm * 32 + ma * 16 + (l & 15);
                uint32_t ad = st + arow * Q_LDA + akb;
                ldsm4(aH[ma], ad);
            }
            {
                const int mloc = l >> 3;   // matrix index 0..3
#pragma unroll
                for (int p = 0; p < 2; p++) {
                    const int brow = wn * 32 + p * 16 + ((mloc >> 1) << 3) + (l & 7);
                    const uint32_t bkb = (ks * 16 + (mloc & 1) * 8) * 2;
                    uint32_t r[4];
                    ldsm4(r, st + Q_TILE + brow * Q_LDA + bkb);
                    bb[2 * p][0] = r[0]; bb[2 * p][1] = r[1];
                    bb[2 * p + 1][0] = r[2]; bb[2 * p + 1][1] = r[3];
                }
            }
#pragma unroll
            for (int ma = 0; ma < 2; ma++)
#pragma unroll
                for (int na = 0; na < 4; na++)
                    mma_f16(c[ma][na], aH[ma], bb[na]);
        }
        // no trailing sync: next iteration's top sync orders reuse of this stage
        s = (s + 1 >= Q_NSTG) ? 0 : (s + 1);
    }

    const float gv = gam[0];
    const float* X = x + (size_t)b * MDIM * DDIM;
    float* Y = out + (size_t)b * MDIM * DDIM;
#pragma unroll
    for (int ma = 0; ma < 2; ma++) {
        const int row0 = m0 + wm * 32 + ma * 16 + (l >> 2);
#pragma unroll
        for (int na = 0; na < 4; na++) {
            const int col = d0 + wn * 32 + na * 8 + (l & 3) * 2;
            {
                float2 xv = *reinterpret_cast<const float2*>(X + (size_t)row0 * DDIM + col);
                *reinterpret_cast<float2*>(Y + (size_t)row0 * DDIM + col) =
                    make_float2(gv * c[ma][na][0] + xv.x, gv * c[ma][na][1] + xv.y);
            }
            {
                float2 xv = *reinterpret_cast<const float2*>(X + (size_t)(row0 + 8) * DDIM + col);
                *reinterpret_cast<float2*>(Y + (size_t)(row0 + 8) * DDIM + col) =
                    make_float2(gv * c[ma][na][2] + xv.x, gv * c[ma][na][3] + xv.y);
            }
        }
    }
}

// ---------------------------------------------------------------------------
extern "C" void kernel_launch(void* const* d_in, const int* in_sizes, int n_in,
                              void* d_out, int out_size) {
    const float* x     = (const float*)d_in[0];
    const float* gamma = (const float*)d_in[1];
    float* out = (float*)d_out;

    cudaFuncSetAttribute(gram_mma_kernel, cudaFuncAttributeMaxDynamicSharedMemorySize, G_SMEM);
    cudaFuncSetAttribute(gemm2_mma_kernel, cudaFuncAttributeMaxDynamicSharedMemorySize, Q_SMEM);

    split_kernel<<<4096, 256>>>(x);
    gram_mma_kernel<<<dim3(10, KSPLIT, BATCH), 512, G_SMEM>>>();
    softmax_kernel<<<dim3(DDIM, BATCH), 256>>>();
    gemm2_mma_kernel<<<dim3(4, MDIM / 128, BATCH), 512, Q_SMEM>>>(x, gamma, out);
}